// round 1
// baseline (speedup 1.0000x reference)
#include <cuda_runtime.h>

#define Bq 64
#define Hq 1024
#define DIN 768
#define TAUD 500
#define Lq 127        // sequence steps = 1 + (SEQ_LEN-2)
#define SEQLEN 128

// -------- scratch (device globals: allocation-free) --------
__device__ float g_pooled[Bq * DIN];
__device__ float g_enc[Bq * Hq];
__device__ float g_h0[2][Bq * Hq];
__device__ float g_h1[2][Bq * Hq];
__device__ float g_c0[Bq * Hq];
__device__ float g_c1[Bq * Hq];
__device__ float g_outs[Lq * Bq * Hq];   // [t][b][h]

__device__ __forceinline__ float sigf(float x) { return 1.0f / (1.0f + __expf(-x)); }

// -------- zero LSTM state --------
__global__ void init_state_kernel() {
    int i = blockIdx.x * blockDim.x + threadIdx.x;   // 65536 threads
    g_h0[0][i] = 0.f;
    g_h1[0][i] = 0.f;
    g_c0[i] = 0.f;
    g_c1[i] = 0.f;
}

// -------- mean-pool audio over time: [B,T,DIN] -> [B,DIN] --------
__global__ void pool_kernel(const float* __restrict__ audio) {
    int i = blockIdx.x * blockDim.x + threadIdx.x;   // B*DIN = 49152
    int b = i / DIN, d = i % DIN;
    const float* p = audio + (size_t)b * TAUD * DIN + d;
    float s = 0.f;
#pragma unroll 5
    for (int t = 0; t < TAUD; t++) s += p[(size_t)t * DIN];
    g_pooled[i] = s * (1.0f / TAUD);
}

// -------- generic NT GEMM: C[m,n] = sum_k A[m,k] * W[n,k] + bias[n] --------
// mode 0: A = g_pooled (K=768), C = g_enc  (direct [m*H+n])
// mode 1: A = g_outs   (K=1024), C = Cext with logits remap:
//         row m = t*64+b  ->  out[((b*Lq)+t)*Hq + n]
__global__ void gemm_nt_kernel(int mode, const float* __restrict__ Bw,
                               const float* __restrict__ bias,
                               float* __restrict__ Cext, int K) {
    const float* A = (mode == 0) ? g_pooled : g_outs;
    __shared__ float As[64][17];
    __shared__ float Bs[64][17];
    int tid = threadIdx.x;               // 256 threads
    int nblk = blockIdx.x, mblk = blockIdx.y;
    int tn = tid & 15, tm = tid >> 4;
    int n0 = tn * 4, m0 = tm * 4;
    float acc[4][4] = {};

    for (int k0 = 0; k0 < K; k0 += 16) {
#pragma unroll
        for (int q = 0; q < 4; q++) {
            int p = tid + 256 * q;       // 1024 elements per tile
            int r = p >> 4, cc = p & 15;
            As[r][cc] = A[(size_t)(mblk * 64 + r) * K + k0 + cc];
            Bs[r][cc] = Bw[(size_t)(nblk * 64 + r) * K + k0 + cc];
        }
        __syncthreads();
#pragma unroll
        for (int k = 0; k < 16; k++) {
            float av[4], bv[4];
#pragma unroll
            for (int i = 0; i < 4; i++) av[i] = As[m0 + i][k];
#pragma unroll
            for (int j = 0; j < 4; j++) bv[j] = Bs[n0 + j][k];
#pragma unroll
            for (int i = 0; i < 4; i++)
#pragma unroll
                for (int j = 0; j < 4; j++) acc[i][j] += av[i] * bv[j];
        }
        __syncthreads();
    }

#pragma unroll
    for (int i = 0; i < 4; i++) {
        int m = mblk * 64 + m0 + i;
#pragma unroll
        for (int j = 0; j < 4; j++) {
            int n = nblk * 64 + n0 + j;
            float v = acc[i][j] + bias[n];
            if (mode == 0) {
                g_enc[m * Hq + n] = v;
            } else {
                int tt = m >> 6, bb = m & 63;
                Cext[((size_t)bb * Lq + tt) * Hq + n] = v;
            }
        }
    }
}

// -------- fused LSTM step (one layer): gate GEMM + pointwise --------
// Block = 128 threads, covers M=64 (batch) x N=32 (4 gates x 8 hidden units).
// layer 0: gates = h0_prev @ W_hh0.T  [+ audio_enc @ W_ih0.T if t==0,
//          else + W_ih0[:, text[b,t]] gather in epilogue]
// layer 1: gates = h0_cur @ W_ih1.T + h1_prev @ W_hh1.T
__global__ void lstm_step_kernel(int t, int layer,
                                 const float* __restrict__ W1,
                                 const float* __restrict__ W2,
                                 const float* __restrict__ Wemb,
                                 const int* __restrict__ text,
                                 const float* __restrict__ b_ih,
                                 const float* __restrict__ b_hh) {
    __shared__ float Xs[64][17];
    __shared__ float Ws[32][17];
    __shared__ float gsm[64][33];

    int tid = threadIdx.x;               // 128 threads
    int j0 = blockIdx.x * 8;             // hidden-unit group, 128 blocks

    int par = t & 1;
    const float* X1;
    const float* X2;
    float* cbuf;
    float* hout;
    if (layer == 0) {
        X1 = g_h0[par];
        X2 = (t == 0) ? g_enc : nullptr;
        cbuf = g_c0;
        hout = g_h0[par ^ 1];
    } else {
        X1 = g_h0[par ^ 1];              // layer-0 output of this step
        X2 = g_h1[par];
        cbuf = g_c1;
        hout = g_h1[par ^ 1];
    }

    int tn = tid & 7, tm = tid >> 3;
    int n0 = tn * 4, m0 = tm * 4;
    float acc[4][4] = {};

    for (int phase = 0; phase < 2; phase++) {
        const float* X = phase ? X2 : X1;
        const float* W = phase ? W2 : W1;
        if (X == nullptr) break;
        for (int k0 = 0; k0 < Hq; k0 += 16) {
#pragma unroll
            for (int q = 0; q < 8; q++) {        // 1024 X elems
                int p = tid + 128 * q;
                int r = p >> 4, cc = p & 15;
                Xs[r][cc] = X[(size_t)r * Hq + k0 + cc];
            }
#pragma unroll
            for (int q = 0; q < 4; q++) {        // 512 W elems
                int p = tid + 128 * q;
                int r = p >> 4, cc = p & 15;
                int wr = (r >> 3) * Hq + j0 + (r & 7);   // gate*H + j
                Ws[r][cc] = W[(size_t)wr * Hq + k0 + cc];
            }
            __syncthreads();
#pragma unroll
            for (int k = 0; k < 16; k++) {
                float xv[4], wv[4];
#pragma unroll
                for (int i = 0; i < 4; i++) xv[i] = Xs[m0 + i][k];
#pragma unroll
                for (int j = 0; j < 4; j++) wv[j] = Ws[n0 + j][k];
#pragma unroll
                for (int i = 0; i < 4; i++)
#pragma unroll
                    for (int j = 0; j < 4; j++) acc[i][j] += xv[i] * wv[j];
            }
            __syncthreads();
        }
    }

    // stage gates into smem so epilogue sees all 4 gates per (m, j)
#pragma unroll
    for (int i = 0; i < 4; i++)
#pragma unroll
        for (int j = 0; j < 4; j++) gsm[m0 + i][n0 + j] = acc[i][j];
    __syncthreads();

    bool useEmb = (layer == 0 && t > 0);
#pragma unroll
    for (int q = 0; q < 4; q++) {
        int cell = tid + 128 * q;        // 512 cells = 64 m x 8 jj
        int m = cell & 63, jj = cell >> 6;
        int j = j0 + jj;
        float vi = gsm[m][jj]      + b_ih[j]          + b_hh[j];
        float vf = gsm[m][8 + jj]  + b_ih[Hq + j]     + b_hh[Hq + j];
        float vg = gsm[m][16 + jj] + b_ih[2 * Hq + j] + b_hh[2 * Hq + j];
        float vo = gsm[m][24 + jj] + b_ih[3 * Hq + j] + b_hh[3 * Hq + j];
        if (useEmb) {
            int ix = text[m * SEQLEN + t];
            vi += Wemb[(size_t)j * Hq + ix];
            vf += Wemb[(size_t)(Hq + j) * Hq + ix];
            vg += Wemb[(size_t)(2 * Hq + j) * Hq + ix];
            vo += Wemb[(size_t)(3 * Hq + j) * Hq + ix];
        }
        float ig = sigf(vi), fg = sigf(vf), gg = tanhf(vg), og = sigf(vo);
        float cn = fg * cbuf[m * Hq + j] + ig * gg;
        cbuf[m * Hq + j] = cn;
        float hv = og * tanhf(cn);
        hout[m * Hq + j] = hv;
        if (layer == 1) g_outs[(size_t)t * Bq * Hq + m * Hq + j] = hv;
    }
}

// -------- host launch (graph-capturable: kernels only) --------
extern "C" void kernel_launch(void* const* d_in, const int* in_sizes, int n_in,
                              void* d_out, int out_size) {
    const float* audio  = (const float*)d_in[0];
    const int*   text   = (const int*)d_in[1];
    const float* W_proj = (const float*)d_in[2];
    const float* b_proj = (const float*)d_in[3];
    const float* W_ih0  = (const float*)d_in[4];
    const float* W_hh0  = (const float*)d_in[5];
    const float* b_ih0  = (const float*)d_in[6];
    const float* b_hh0  = (const float*)d_in[7];
    const float* W_ih1  = (const float*)d_in[8];
    const float* W_hh1  = (const float*)d_in[9];
    const float* b_ih1  = (const float*)d_in[10];
    const float* b_hh1  = (const float*)d_in[11];
    const float* W_out  = (const float*)d_in[12];
    const float* b_out  = (const float*)d_in[13];
    float* out = (float*)d_out;

    init_state_kernel<<<256, 256>>>();
    pool_kernel<<<(Bq * DIN) / 128, 128>>>(audio);
    // audio_enc = pooled @ W_proj.T + b_proj   (M=64, N=1024, K=768)
    gemm_nt_kernel<<<dim3(16, 1), 256>>>(0, W_proj, b_proj, nullptr, DIN);

    for (int t = 0; t < Lq; t++) {
        lstm_step_kernel<<<128, 128>>>(t, 0, W_hh0, W_ih0, W_ih0, text, b_ih0, b_hh0);
        lstm_step_kernel<<<128, 128>>>(t, 1, W_ih1, W_hh1, nullptr, nullptr, b_ih1, b_hh1);
    }

    // logits = outs @ W_out.T + b_out   (M = 127*64 = 8128, N=1024, K=1024)
    gemm_nt_kernel<<<dim3(16, Lq), 256>>>(1, W_out, b_out, out, Hq);
}

// round 2
// speedup vs baseline: 1.8041x; 1.8041x over previous
#include <cuda_runtime.h>

#define Bq 64
#define Hq 1024
#define DIN 768
#define TAUD 500
#define Lq 127        // sequence steps = 1 + (SEQ_LEN-2)
#define SEQLEN 128
#define KC 32         // k-chunk per smem tile

// -------- scratch (device globals: allocation-free) --------
__device__ float g_pooled[Bq * DIN];
__device__ float g_enc[Bq * Hq];
__device__ float g_h0[2][Bq * Hq];
__device__ float g_h1[2][Bq * Hq];
__device__ float g_c0[Bq * Hq];
__device__ float g_c1[Bq * Hq];
__device__ float g_outs[Lq * Bq * Hq];   // [t][b][h]

__device__ __forceinline__ float sigf(float x) { return 1.0f / (1.0f + __expf(-x)); }

// -------- zero LSTM state --------
__global__ void init_state_kernel() {
    int i = blockIdx.x * blockDim.x + threadIdx.x;   // 65536 threads
    g_h0[0][i] = 0.f;
    g_h1[0][i] = 0.f;
    g_c0[i] = 0.f;
    g_c1[i] = 0.f;
}

// -------- mean-pool audio over time: [B,T,DIN] -> [B,DIN] --------
__global__ void pool_kernel(const float* __restrict__ audio) {
    int i = blockIdx.x * blockDim.x + threadIdx.x;   // B*DIN = 49152
    int b = i / DIN, d = i % DIN;
    const float* p = audio + (size_t)b * TAUD * DIN + d;
    float s = 0.f;
#pragma unroll 5
    for (int t = 0; t < TAUD; t++) s += p[(size_t)t * DIN];
    g_pooled[i] = s * (1.0f / TAUD);
}

// -------- generic NT GEMM: C[m,n] = sum_k A[m,k] * W[n,k] + bias[n] --------
__global__ void gemm_nt_kernel(int mode, const float* __restrict__ Bw,
                               const float* __restrict__ bias,
                               float* __restrict__ Cext, int K) {
    const float* A = (mode == 0) ? g_pooled : g_outs;
    __shared__ float As[64][17];
    __shared__ float Bs[64][17];
    int tid = threadIdx.x;               // 256 threads
    int nblk = blockIdx.x, mblk = blockIdx.y;
    int tn = tid & 15, tm = tid >> 4;
    int n0 = tn * 4, m0 = tm * 4;
    float acc[4][4] = {};

    for (int k0 = 0; k0 < K; k0 += 16) {
#pragma unroll
        for (int q = 0; q < 4; q++) {
            int p = tid + 256 * q;       // 1024 elements per tile
            int r = p >> 4, cc = p & 15;
            As[r][cc] = A[(size_t)(mblk * 64 + r) * K + k0 + cc];
            Bs[r][cc] = Bw[(size_t)(nblk * 64 + r) * K + k0 + cc];
        }
        __syncthreads();
#pragma unroll
        for (int k = 0; k < 16; k++) {
            float av[4], bv[4];
#pragma unroll
            for (int i = 0; i < 4; i++) av[i] = As[m0 + i][k];
#pragma unroll
            for (int j = 0; j < 4; j++) bv[j] = Bs[n0 + j][k];
#pragma unroll
            for (int i = 0; i < 4; i++)
#pragma unroll
                for (int j = 0; j < 4; j++) acc[i][j] += av[i] * bv[j];
        }
        __syncthreads();
    }

#pragma unroll
    for (int i = 0; i < 4; i++) {
        int m = mblk * 64 + m0 + i;
#pragma unroll
        for (int j = 0; j < 4; j++) {
            int n = nblk * 64 + n0 + j;
            float v = acc[i][j] + bias[n];
            if (mode == 0) {
                g_enc[m * Hq + n] = v;
            } else {
                int tt = m >> 6, bb = m & 63;
                Cext[((size_t)bb * Lq + tt) * Hq + n] = v;
            }
        }
    }
}

// -------- fused LSTM step(s) --------
// block = 256 threads = 2 k-groups of 128. Each (role,blk) covers the
// M=64 x N=32 gate tile (4 gates x 8 hidden units) for one layer-step.
// mode 0: all 128 blocks do layer0 at step t
// mode 1: blocks 0..127 do layer1 at step t, blocks 128..255 do layer0 at t+1
// mode 2: all 128 blocks do layer1 at step t
__global__ __launch_bounds__(256, 2)
void lstm_dual_kernel(int t, int mode,
                      const float* __restrict__ Wih0, const float* __restrict__ Whh0,
                      const float* __restrict__ bih0, const float* __restrict__ bhh0,
                      const float* __restrict__ Wih1, const float* __restrict__ Whh1,
                      const float* __restrict__ bih1, const float* __restrict__ bhh1,
                      const int* __restrict__ text) {
    __shared__ float Xs[2][64][KC + 1];
    __shared__ float Ws[2][32][KC + 1];
    __shared__ float gsm[64][KC + 1];

    int tid = threadIdx.x;
    int grp = tid >> 7;          // 0 or 1: K-half
    int ltid = tid & 127;

    bool isL0; int step;
    if (mode == 0)       { isL0 = true;  step = t; }
    else if (mode == 2)  { isL0 = false; step = t; }
    else {
        if (blockIdx.x < 128) { isL0 = false; step = t; }
        else                  { isL0 = true;  step = t + 1; }
    }
    int blk = blockIdx.x & 127;
    int j0 = blk * 8;

    int par = step & 1;
    const float* X1; const float* X2;
    const float* W1; const float* W2;
    const float* b_ih; const float* b_hh;
    float* cbuf; float* hout;
    bool useEmb = false;
    if (isL0) {
        X1 = g_h0[par]; X2 = (step == 0) ? g_enc : nullptr;
        W1 = Whh0;      W2 = Wih0;
        b_ih = bih0;    b_hh = bhh0;
        cbuf = g_c0;    hout = g_h0[par ^ 1];
        useEmb = (step > 0);
    } else {
        X1 = g_h0[par ^ 1]; X2 = g_h1[par];
        W1 = Wih1;          W2 = Whh1;
        b_ih = bih1;        b_hh = bhh1;
        cbuf = g_c1;        hout = g_h1[par ^ 1];
    }

    // thread micro-tile: 4x4 over M=64 x N=32
    int tn = ltid & 7, tm = ltid >> 3;
    int n0 = tn * 4, m0 = tm * 4;
    float acc[4][4] = {};

    // global-load assignments (per group, per KC tile)
    int xr = ltid >> 1;                 // X row 0..63
    int xc = (ltid & 1) * 16;           // X col base within KC
    int wrr = ltid >> 2;                // W logical row 0..31
    int wc = (ltid & 3) * 8;            // W col base within KC
    int wrow = (wrr >> 3) * Hq + j0 + (wrr & 7);   // gate*H + unit

    for (int phase = 0; phase < 2; phase++) {
        const float* X = phase ? X2 : X1;
        const float* W = phase ? W2 : W1;
        if (X == nullptr) break;

        const int kbase = grp * 512;
        float4 xv[4], wv[2];
        // prefetch tile 0
        {
            const float* xp = X + (size_t)xr * Hq + kbase + xc;
            const float* wp = W + (size_t)wrow * Hq + kbase + wc;
#pragma unroll
            for (int i = 0; i < 4; i++) xv[i] = ((const float4*)xp)[i];
#pragma unroll
            for (int i = 0; i < 2; i++) wv[i] = ((const float4*)wp)[i];
        }

        for (int it = 0; it < 512 / KC; it++) {
            // store staged regs -> smem
#pragma unroll
            for (int i = 0; i < 4; i++) {
                Xs[grp][xr][xc + 4 * i + 0] = xv[i].x;
                Xs[grp][xr][xc + 4 * i + 1] = xv[i].y;
                Xs[grp][xr][xc + 4 * i + 2] = xv[i].z;
                Xs[grp][xr][xc + 4 * i + 3] = xv[i].w;
            }
#pragma unroll
            for (int i = 0; i < 2; i++) {
                Ws[grp][wrr][wc + 4 * i + 0] = wv[i].x;
                Ws[grp][wrr][wc + 4 * i + 1] = wv[i].y;
                Ws[grp][wrr][wc + 4 * i + 2] = wv[i].z;
                Ws[grp][wrr][wc + 4 * i + 3] = wv[i].w;
            }
            __syncthreads();

            // prefetch next tile
            if (it + 1 < 512 / KC) {
                int kk = kbase + (it + 1) * KC;
                const float* xp = X + (size_t)xr * Hq + kk + xc;
                const float* wp = W + (size_t)wrow * Hq + kk + wc;
#pragma unroll
                for (int i = 0; i < 4; i++) xv[i] = ((const float4*)xp)[i];
#pragma unroll
                for (int i = 0; i < 2; i++) wv[i] = ((const float4*)wp)[i];
            }

            // compute
#pragma unroll
            for (int k = 0; k < KC; k++) {
                float av[4], bv[4];
#pragma unroll
                for (int i = 0; i < 4; i++) av[i] = Xs[grp][m0 + i][k];
#pragma unroll
                for (int j = 0; j < 4; j++) bv[j] = Ws[grp][n0 + j][k];
#pragma unroll
                for (int i = 0; i < 4; i++)
#pragma unroll
                    for (int j = 0; j < 4; j++) acc[i][j] += av[i] * bv[j];
            }
            __syncthreads();
        }
    }

    // reduce across k-groups into gsm
    if (grp == 1) {
#pragma unroll
        for (int i = 0; i < 4; i++)
#pragma unroll
            for (int j = 0; j < 4; j++) gsm[m0 + i][n0 + j] = acc[i][j];
    }
    __syncthreads();
    if (grp == 0) {
#pragma unroll
        for (int i = 0; i < 4; i++)
#pragma unroll
            for (int j = 0; j < 4; j++)
                gsm[m0 + i][n0 + j] += acc[i][j];
    }
    __syncthreads();

    // pointwise epilogue: 512 cells over 256 threads
#pragma unroll
    for (int q = 0; q < 2; q++) {
        int cell = tid + 256 * q;
        int m = cell & 63, jj = cell >> 6;
        int j = j0 + jj;
        float vi = gsm[m][jj]      + b_ih[j]          + b_hh[j];
        float vf = gsm[m][8 + jj]  + b_ih[Hq + j]     + b_hh[Hq + j];
        float vg = gsm[m][16 + jj] + b_ih[2 * Hq + j] + b_hh[2 * Hq + j];
        float vo = gsm[m][24 + jj] + b_ih[3 * Hq + j] + b_hh[3 * Hq + j];
        if (useEmb) {
            int ix = text[m * SEQLEN + step];
            vi += Wih0[(size_t)j * Hq + ix];
            vf += Wih0[(size_t)(Hq + j) * Hq + ix];
            vg += Wih0[(size_t)(2 * Hq + j) * Hq + ix];
            vo += Wih0[(size_t)(3 * Hq + j) * Hq + ix];
        }
        float ig = sigf(vi), fg = sigf(vf), gg = tanhf(vg), og = sigf(vo);
        float cn = fg * cbuf[m * Hq + j] + ig * gg;
        cbuf[m * Hq + j] = cn;
        float hv = og * tanhf(cn);
        hout[m * Hq + j] = hv;
        if (!isL0) g_outs[(size_t)step * Bq * Hq + m * Hq + j] = hv;
    }
}

// -------- host launch (graph-capturable: kernels only) --------
extern "C" void kernel_launch(void* const* d_in, const int* in_sizes, int n_in,
                              void* d_out, int out_size) {
    const float* audio  = (const float*)d_in[0];
    const int*   text   = (const int*)d_in[1];
    const float* W_proj = (const float*)d_in[2];
    const float* b_proj = (const float*)d_in[3];
    const float* W_ih0  = (const float*)d_in[4];
    const float* W_hh0  = (const float*)d_in[5];
    const float* b_ih0  = (const float*)d_in[6];
    const float* b_hh0  = (const float*)d_in[7];
    const float* W_ih1  = (const float*)d_in[8];
    const float* W_hh1  = (const float*)d_in[9];
    const float* b_ih1  = (const float*)d_in[10];
    const float* b_hh1  = (const float*)d_in[11];
    const float* W_out  = (const float*)d_in[12];
    const float* b_out  = (const float*)d_in[13];
    float* out = (float*)d_out;

    init_state_kernel<<<256, 256>>>();
    pool_kernel<<<(Bq * DIN) / 128, 128>>>(audio);
    // audio_enc = pooled @ W_proj.T + b_proj   (M=64, N=1024, K=768)
    gemm_nt_kernel<<<dim3(16, 1), 256>>>(0, W_proj, b_proj, nullptr, DIN);

    // step 0, layer 0 alone
    lstm_dual_kernel<<<128, 256>>>(0, 0, W_ih0, W_hh0, b_ih0, b_hh0,
                                   W_ih1, W_hh1, b_ih1, b_hh1, text);
    // fused: layer1(t) + layer0(t+1)
    for (int t = 0; t <= 125; t++)
        lstm_dual_kernel<<<256, 256>>>(t, 1, W_ih0, W_hh0, b_ih0, b_hh0,
                                       W_ih1, W_hh1, b_ih1, b_hh1, text);
    // final layer1(126)
    lstm_dual_kernel<<<128, 256>>>(126, 2, W_ih0, W_hh0, b_ih0, b_hh0,
                                   W_ih1, W_hh1, b_ih1, b_hh1, text);

    // logits = outs @ W_out.T + b_out   (M = 127*64 = 8128, N=1024, K=1024)
    gemm_nt_kernel<<<dim3(16, Lq), 256>>>(1, W_out, b_out, out, Hq);
}

// round 3
// speedup vs baseline: 2.4158x; 1.3391x over previous
#include <cuda_runtime.h>
#include <cstdint>

#define Bq 64
#define Hq 1024
#define DIN 768
#define TAUD 500
#define Lq 127        // sequence steps = 1 + (SEQ_LEN-2)
#define SEQLEN 128
#define KC 32         // k-chunk per smem tile

// -------- scratch (device globals: allocation-free) --------
__device__ float g_pooled[Bq * DIN];
__device__ float g_enc[Bq * Hq];
__device__ float g_h0[2][Bq * Hq];
__device__ float g_h1[2][Bq * Hq];
__device__ float g_c0[Bq * Hq];
__device__ float g_c1[Bq * Hq];
__device__ float g_outs[Lq * Bq * Hq];   // [t][b][h]

__device__ __forceinline__ float sigf(float x) { return 1.0f / (1.0f + __expf(-x)); }

__device__ __forceinline__ uint32_t f2tf32(float f) {
    uint32_t u;
    asm("cvt.rna.tf32.f32 %0, %1;" : "=r"(u) : "f"(f));
    return u;
}

__device__ __forceinline__ void mma_tf32(float& c0, float& c1, float& c2, float& c3,
                                         uint32_t a0, uint32_t a1, uint32_t a2, uint32_t a3,
                                         uint32_t b0, uint32_t b1) {
    asm volatile("mma.sync.aligned.m16n8k8.row.col.f32.tf32.tf32.f32 "
                 "{%0,%1,%2,%3}, {%4,%5,%6,%7}, {%8,%9}, {%0,%1,%2,%3};"
                 : "+f"(c0), "+f"(c1), "+f"(c2), "+f"(c3)
                 : "r"(a0), "r"(a1), "r"(a2), "r"(a3), "r"(b0), "r"(b1));
}

// -------- zero LSTM state --------
__global__ void init_state_kernel() {
    int i = blockIdx.x * blockDim.x + threadIdx.x;   // 65536 threads
    g_h0[0][i] = 0.f;
    g_h1[0][i] = 0.f;
    g_c0[i] = 0.f;
    g_c1[i] = 0.f;
}

// -------- mean-pool audio over time: [B,T,DIN] -> [B,DIN] --------
__global__ void pool_kernel(const float* __restrict__ audio) {
    int i = blockIdx.x * blockDim.x + threadIdx.x;   // B*DIN = 49152
    int b = i / DIN, d = i % DIN;
    const float* p = audio + (size_t)b * TAUD * DIN + d;
    float s = 0.f;
#pragma unroll 5
    for (int t = 0; t < TAUD; t++) s += p[(size_t)t * DIN];
    g_pooled[i] = s * (1.0f / TAUD);
}

// ============ tf32 tensor-core NT GEMM: C = A @ W^T + bias ============
// Tile 64x64 per block (256 thr / 8 warps), warp tile m16 x n32 (4 n-subtiles).
// mode 0: A = g_pooled (K=768), C = g_enc (direct [m*Hq+n])
// mode 1: A = g_outs   (K=1024), C = out with logits remap:
//         row m = t*64+b  ->  out[((b*Lq)+t)*Hq + n]
__global__ __launch_bounds__(256, 2)
void gemm_tf32_kernel(int mode, const float* __restrict__ Bw,
                      const float* __restrict__ bias,
                      float* __restrict__ Cext, int K) {
    __shared__ uint32_t As[64][36];
    __shared__ uint32_t Bs[64][36];
    const float* A = (mode == 0) ? g_pooled : g_outs;

    int tid = threadIdx.x;
    int lane = tid & 31, warp = tid >> 5;
    int nblk = blockIdx.x, mblk = blockIdx.y;

    int m0 = (warp & 3) * 16;
    int n0 = (warp >> 2) * 32;
    float acc[4][4] = {};

    int row = tid >> 3;            // 0..31 ; second elem row+32
    int c4 = (tid & 7) * 4;        // float4 col within KC

    const float* ap0 = A + (size_t)(mblk * 64 + row) * K + c4;
    const float* ap1 = A + (size_t)(mblk * 64 + row + 32) * K + c4;
    const float* bp0 = Bw + (size_t)(nblk * 64 + row) * K + c4;
    const float* bp1 = Bw + (size_t)(nblk * 64 + row + 32) * K + c4;

    int nC = K / KC;
    float4 xv0 = *(const float4*)ap0;
    float4 xv1 = *(const float4*)ap1;
    float4 wv0 = *(const float4*)bp0;
    float4 wv1 = *(const float4*)bp1;

    for (int c = 0; c < nC; c++) {
        uint4 u;
        u.x = f2tf32(xv0.x); u.y = f2tf32(xv0.y); u.z = f2tf32(xv0.z); u.w = f2tf32(xv0.w);
        *(uint4*)&As[row][c4] = u;
        u.x = f2tf32(xv1.x); u.y = f2tf32(xv1.y); u.z = f2tf32(xv1.z); u.w = f2tf32(xv1.w);
        *(uint4*)&As[row + 32][c4] = u;
        u.x = f2tf32(wv0.x); u.y = f2tf32(wv0.y); u.z = f2tf32(wv0.z); u.w = f2tf32(wv0.w);
        *(uint4*)&Bs[row][c4] = u;
        u.x = f2tf32(wv1.x); u.y = f2tf32(wv1.y); u.z = f2tf32(wv1.z); u.w = f2tf32(wv1.w);
        *(uint4*)&Bs[row + 32][c4] = u;
        __syncthreads();

        if (c + 1 < nC) {
            int k0 = (c + 1) * KC;
            xv0 = *(const float4*)(ap0 + k0);
            xv1 = *(const float4*)(ap1 + k0);
            wv0 = *(const float4*)(bp0 + k0);
            wv1 = *(const float4*)(bp1 + k0);
        }

#pragma unroll
        for (int ks = 0; ks < 4; ks++) {
            int kk = ks * 8;
            uint32_t a0 = As[m0 + (lane >> 2)][kk + (lane & 3)];
            uint32_t a1 = As[m0 + (lane >> 2) + 8][kk + (lane & 3)];
            uint32_t a2 = As[m0 + (lane >> 2)][kk + (lane & 3) + 4];
            uint32_t a3 = As[m0 + (lane >> 2) + 8][kk + (lane & 3) + 4];
#pragma unroll
            for (int nt = 0; nt < 4; nt++) {
                uint32_t b0 = Bs[n0 + nt * 8 + (lane >> 2)][kk + (lane & 3)];
                uint32_t b1 = Bs[n0 + nt * 8 + (lane >> 2)][kk + (lane & 3) + 4];
                mma_tf32(acc[nt][0], acc[nt][1], acc[nt][2], acc[nt][3],
                         a0, a1, a2, a3, b0, b1);
            }
        }
        __syncthreads();
    }

    // epilogue: direct float2 stores with bias
#pragma unroll
    for (int nt = 0; nt < 4; nt++) {
        int r = mblk * 64 + m0 + (lane >> 2);
        int cc = nblk * 64 + n0 + nt * 8 + (lane & 3) * 2;
        float bz0 = bias[cc], bz1 = bias[cc + 1];
        float2 v0 = make_float2(acc[nt][0] + bz0, acc[nt][1] + bz1);
        float2 v1 = make_float2(acc[nt][2] + bz0, acc[nt][3] + bz1);
        if (mode == 0) {
            *(float2*)&g_enc[r * Hq + cc] = v0;
            *(float2*)&g_enc[(r + 8) * Hq + cc] = v1;
        } else {
            int tt = r >> 6, bb = r & 63;
            *(float2*)&Cext[((size_t)bb * Lq + tt) * Hq + cc] = v0;
            int r8 = r + 8;
            tt = r8 >> 6; bb = r8 & 63;
            *(float2*)&Cext[((size_t)bb * Lq + tt) * Hq + cc] = v1;
        }
    }
}

// ============ fused LSTM step(s), tf32 tensor cores ============
// Block: 256 thr / 8 warps computes M=64 x N=64 gate tile (4 gates x 16 units).
// mode 0: 64 blocks, layer0 @ t       (phase2 = audio enc GEMM)
// mode 1: 128 blocks: 0..63 layer1 @ t, 64..127 layer0 @ t+1
// mode 2: 64 blocks, layer1 @ t
__global__ __launch_bounds__(256, 2)
void lstm_tf32_kernel(int t, int mode,
                      const float* __restrict__ Wih0, const float* __restrict__ Whh0,
                      const float* __restrict__ bih0, const float* __restrict__ bhh0,
                      const float* __restrict__ Wih1, const float* __restrict__ Whh1,
                      const float* __restrict__ bih1, const float* __restrict__ bhh1,
                      const int* __restrict__ text) {
    __shared__ uint32_t Xs[64][36];
    __shared__ uint32_t Ws[64][36];
    __shared__ float gsm[64][68];

    int tid = threadIdx.x;
    int lane = tid & 31, warp = tid >> 5;

    bool isL0; int step;
    if (mode == 0)      { isL0 = true;  step = t; }
    else if (mode == 2) { isL0 = false; step = t; }
    else {
        if (blockIdx.x < 64) { isL0 = false; step = t; }
        else                 { isL0 = true;  step = t + 1; }
    }
    int blk = blockIdx.x & 63;
    int j0 = blk * 16;

    int par = step & 1;
    const float* X1; const float* X2;
    const float* W1; const float* W2;
    const float* b_ih; const float* b_hh;
    float* cbuf; float* hout;
    bool useEmb = false;
    if (isL0) {
        X1 = g_h0[par]; X2 = (step == 0) ? g_enc : nullptr;
        W1 = Whh0;      W2 = Wih0;
        b_ih = bih0;    b_hh = bhh0;
        cbuf = g_c0;    hout = g_h0[par ^ 1];
        useEmb = (step > 0);
    } else {
        X1 = g_h0[par ^ 1]; X2 = g_h1[par];
        W1 = Wih1;          W2 = Whh1;
        b_ih = bih1;        b_hh = bhh1;
        cbuf = g_c1;        hout = g_h1[par ^ 1];
    }

    int m0 = (warp & 3) * 16;
    int n0 = (warp >> 2) * 32;
    float acc[4][4] = {};

    int row = tid >> 3;            // 0..31 ; second elem row+32
    int c4 = (tid & 7) * 4;
    // W logical row n -> global row (n>>4)*Hq + j0 + (n&15)
    int wr0 = (row >> 4) * Hq + j0 + (row & 15);
    int wr1 = ((row + 32) >> 4) * Hq + j0 + ((row + 32) & 15);

    for (int phase = 0; phase < 2; phase++) {
        const float* X = phase ? X2 : X1;
        const float* W = phase ? W2 : W1;
        if (X == nullptr) break;

        const float* xp0 = X + (size_t)row * Hq + c4;
        const float* xp1 = X + (size_t)(row + 32) * Hq + c4;
        const float* wp0 = W + (size_t)wr0 * Hq + c4;
        const float* wp1 = W + (size_t)wr1 * Hq + c4;

        float4 xv0 = *(const float4*)xp0;
        float4 xv1 = *(const float4*)xp1;
        float4 wv0 = *(const float4*)wp0;
        float4 wv1 = *(const float4*)wp1;

        for (int c = 0; c < Hq / KC; c++) {
            uint4 u;
            u.x = f2tf32(xv0.x); u.y = f2tf32(xv0.y); u.z = f2tf32(xv0.z); u.w = f2tf32(xv0.w);
            *(uint4*)&Xs[row][c4] = u;
            u.x = f2tf32(xv1.x); u.y = f2tf32(xv1.y); u.z = f2tf32(xv1.z); u.w = f2tf32(xv1.w);
            *(uint4*)&Xs[row + 32][c4] = u;
            u.x = f2tf32(wv0.x); u.y = f2tf32(wv0.y); u.z = f2tf32(wv0.z); u.w = f2tf32(wv0.w);
            *(uint4*)&Ws[row][c4] = u;
            u.x = f2tf32(wv1.x); u.y = f2tf32(wv1.y); u.z = f2tf32(wv1.z); u.w = f2tf32(wv1.w);
            *(uint4*)&Ws[row + 32][c4] = u;
            __syncthreads();

            if (c + 1 < Hq / KC) {
                int k0 = (c + 1) * KC;
                xv0 = *(const float4*)(xp0 + k0);
                xv1 = *(const float4*)(xp1 + k0);
                wv0 = *(const float4*)(wp0 + k0);
                wv1 = *(const float4*)(wp1 + k0);
            }

#pragma unroll
            for (int ks = 0; ks < 4; ks++) {
                int kk = ks * 8;
                uint32_t a0 = Xs[m0 + (lane >> 2)][kk + (lane & 3)];
                uint32_t a1 = Xs[m0 + (lane >> 2) + 8][kk + (lane & 3)];
                uint32_t a2 = Xs[m0 + (lane >> 2)][kk + (lane & 3) + 4];
                uint32_t a3 = Xs[m0 + (lane >> 2) + 8][kk + (lane & 3) + 4];
#pragma unroll
                for (int nt = 0; nt < 4; nt++) {
                    uint32_t b0 = Ws[n0 + nt * 8 + (lane >> 2)][kk + (lane & 3)];
                    uint32_t b1 = Ws[n0 + nt * 8 + (lane >> 2)][kk + (lane & 3) + 4];
                    mma_tf32(acc[nt][0], acc[nt][1], acc[nt][2], acc[nt][3],
                             a0, a1, a2, a3, b0, b1);
                }
            }
            __syncthreads();
        }
    }

    // stage gates into smem so epilogue sees all 4 gates per (m, j)
#pragma unroll
    for (int nt = 0; nt < 4; nt++) {
        int r = m0 + (lane >> 2);
        int cc = n0 + nt * 8 + (lane & 3) * 2;
        gsm[r][cc] = acc[nt][0];
        gsm[r][cc + 1] = acc[nt][1];
        gsm[r + 8][cc] = acc[nt][2];
        gsm[r + 8][cc + 1] = acc[nt][3];
    }
    __syncthreads();

    // pointwise epilogue: 1024 cells (64 m x 16 units) over 256 threads
#pragma unroll
    for (int q = 0; q < 4; q++) {
        int cell = tid + 256 * q;
        int m = cell & 63, u = cell >> 6;   // u in 0..15
        int j = j0 + u;
        float vi = gsm[m][u]       + b_ih[j]          + b_hh[j];
        float vf = gsm[m][16 + u]  + b_ih[Hq + j]     + b_hh[Hq + j];
        float vg = gsm[m][32 + u]  + b_ih[2 * Hq + j] + b_hh[2 * Hq + j];
        float vo = gsm[m][48 + u]  + b_ih[3 * Hq + j] + b_hh[3 * Hq + j];
        if (useEmb) {
            int ix = text[m * SEQLEN + step];
            vi += Wih0[(size_t)j * Hq + ix];
            vf += Wih0[(size_t)(Hq + j) * Hq + ix];
            vg += Wih0[(size_t)(2 * Hq + j) * Hq + ix];
            vo += Wih0[(size_t)(3 * Hq + j) * Hq + ix];
        }
        float ig = sigf(vi), fg = sigf(vf), gg = tanhf(vg), og = sigf(vo);
        float cn = fg * cbuf[m * Hq + j] + ig * gg;
        cbuf[m * Hq + j] = cn;
        float hv = og * tanhf(cn);
        hout[m * Hq + j] = hv;
        if (!isL0) g_outs[(size_t)step * Bq * Hq + m * Hq + j] = hv;
    }
}

// -------- host launch (graph-capturable: kernels only) --------
extern "C" void kernel_launch(void* const* d_in, const int* in_sizes, int n_in,
                              void* d_out, int out_size) {
    const float* audio  = (const float*)d_in[0];
    const int*   text   = (const int*)d_in[1];
    const float* W_proj = (const float*)d_in[2];
    const float* b_proj = (const float*)d_in[3];
    const float* W_ih0  = (const float*)d_in[4];
    const float* W_hh0  = (const float*)d_in[5];
    const float* b_ih0  = (const float*)d_in[6];
    const float* b_hh0  = (const float*)d_in[7];
    const float* W_ih1  = (const float*)d_in[8];
    const float* W_hh1  = (const float*)d_in[9];
    const float* b_ih1  = (const float*)d_in[10];
    const float* b_hh1  = (const float*)d_in[11];
    const float* W_out  = (const float*)d_in[12];
    const float* b_out  = (const float*)d_in[13];
    float* out = (float*)d_out;

    init_state_kernel<<<256, 256>>>();
    pool_kernel<<<(Bq * DIN) / 128, 128>>>(audio);
    // audio_enc = pooled @ W_proj.T + b_proj   (M=64, N=1024, K=768)
    gemm_tf32_kernel<<<dim3(16, 1), 256>>>(0, W_proj, b_proj, nullptr, DIN);

    // step 0, layer 0 alone
    lstm_tf32_kernel<<<64, 256>>>(0, 0, W_ih0, W_hh0, b_ih0, b_hh0,
                                  W_ih1, W_hh1, b_ih1, b_hh1, text);
    // fused: layer1(t) + layer0(t+1)
    for (int t = 0; t <= 125; t++)
        lstm_tf32_kernel<<<128, 256>>>(t, 1, W_ih0, W_hh0, b_ih0, b_hh0,
                                       W_ih1, W_hh1, b_ih1, b_hh1, text);
    // final layer1(126)
    lstm_tf32_kernel<<<64, 256>>>(126, 2, W_ih0, W_hh0, b_ih0, b_hh0,
                                  W_ih1, W_hh1, b_ih1, b_hh1, text);

    // logits = outs @ W_out.T + b_out   (M = 127*64 = 8128, N=1024, K=1024)
    gemm_tf32_kernel<<<dim3(16, Lq), 256>>>(1, W_out, b_out, out, Hq);
}

// round 4
// speedup vs baseline: 2.9764x; 1.2321x over previous
#include <cuda_runtime.h>
#include <cstdint>

#define Bq 64
#define Hq 1024
#define DIN 768
#define TAUD 500
#define Lq 127        // sequence steps = 1 + (SEQ_LEN-2)
#define SEQLEN 128
#define KC 32         // k-chunk per smem tile
#define NPB 128       // persistent blocks (<=148 SMs, all co-resident)

// -------- scratch (device globals: allocation-free) --------
__device__ float g_pooled[Bq * DIN];
__device__ float g_enc[Bq * Hq];
__device__ float g_h0[2][Bq * Hq];
__device__ float g_h1[2][Bq * Hq];
__device__ float g_outs[Lq * Bq * Hq];   // [t][b][h]
__device__ unsigned g_bar;

__device__ __forceinline__ float sigf(float x) { return 1.0f / (1.0f + __expf(-x)); }

__device__ __forceinline__ uint32_t f2tf32(float f) {
    uint32_t u;
    asm("cvt.rna.tf32.f32 %0, %1;" : "=r"(u) : "f"(f));
    return u;
}

__device__ __forceinline__ void mma_tf32(float& c0, float& c1, float& c2, float& c3,
                                         uint32_t a0, uint32_t a1, uint32_t a2, uint32_t a3,
                                         uint32_t b0, uint32_t b1) {
    asm volatile("mma.sync.aligned.m16n8k8.row.col.f32.tf32.tf32.f32 "
                 "{%0,%1,%2,%3}, {%4,%5,%6,%7}, {%8,%9}, {%0,%1,%2,%3};"
                 : "+f"(c0), "+f"(c1), "+f"(c2), "+f"(c3)
                 : "r"(a0), "r"(a1), "r"(a2), "r"(a3), "r"(b0), "r"(b1));
}

// grid-wide barrier: monotonic counter, all NPB blocks arrive
__device__ __forceinline__ void grid_sync(unsigned target) {
    __syncthreads();
    if (threadIdx.x == 0) {
        __threadfence();
        atomicAdd(&g_bar, 1u);
        unsigned v;
        do {
            asm volatile("ld.acquire.gpu.u32 %0, [%1];" : "=r"(v) : "l"(&g_bar));
            if (v >= target) break;
            __nanosleep(64);
        } while (true);
    }
    __syncthreads();
}

__global__ void reset_kernel() { g_bar = 0; }

// -------- mean-pool audio over time: [B,T,DIN] -> [B,DIN] --------
__global__ void pool_kernel(const float* __restrict__ audio) {
    int i = blockIdx.x * blockDim.x + threadIdx.x;   // B*DIN = 49152
    int b = i / DIN, d = i % DIN;
    const float* p = audio + (size_t)b * TAUD * DIN + d;
    float s = 0.f;
#pragma unroll 5
    for (int t = 0; t < TAUD; t++) s += __ldcs(p + (size_t)t * DIN);
    g_pooled[i] = s * (1.0f / TAUD);
}

// ============ tf32 tensor-core NT GEMM: C = A @ W^T + bias ============
// mode 0: A = g_pooled (K=768), C = g_enc;  mode 1: A = g_outs (K=1024), logits remap
__global__ __launch_bounds__(256, 2)
void gemm_tf32_kernel(int mode, const float* __restrict__ Bw,
                      const float* __restrict__ bias,
                      float* __restrict__ Cext, int K) {
    __shared__ uint32_t As[64][36];
    __shared__ uint32_t Bs[64][36];
    const float* A = (mode == 0) ? g_pooled : g_outs;

    int tid = threadIdx.x;
    int lane = tid & 31, warp = tid >> 5;
    int nblk = blockIdx.x, mblk = blockIdx.y;

    int m0 = (warp & 3) * 16;
    int n0 = (warp >> 2) * 32;
    float acc[4][4] = {};

    int row = tid >> 3;
    int c4 = (tid & 7) * 4;

    const float* ap0 = A + (size_t)(mblk * 64 + row) * K + c4;
    const float* ap1 = A + (size_t)(mblk * 64 + row + 32) * K + c4;
    const float* bp0 = Bw + (size_t)(nblk * 64 + row) * K + c4;
    const float* bp1 = Bw + (size_t)(nblk * 64 + row + 32) * K + c4;

    int nC = K / KC;
    float4 xv0 = *(const float4*)ap0;
    float4 xv1 = *(const float4*)ap1;
    float4 wv0 = *(const float4*)bp0;
    float4 wv1 = *(const float4*)bp1;

    for (int c = 0; c < nC; c++) {
        uint4 u;
        u.x = f2tf32(xv0.x); u.y = f2tf32(xv0.y); u.z = f2tf32(xv0.z); u.w = f2tf32(xv0.w);
        *(uint4*)&As[row][c4] = u;
        u.x = f2tf32(xv1.x); u.y = f2tf32(xv1.y); u.z = f2tf32(xv1.z); u.w = f2tf32(xv1.w);
        *(uint4*)&As[row + 32][c4] = u;
        u.x = f2tf32(wv0.x); u.y = f2tf32(wv0.y); u.z = f2tf32(wv0.z); u.w = f2tf32(wv0.w);
        *(uint4*)&Bs[row][c4] = u;
        u.x = f2tf32(wv1.x); u.y = f2tf32(wv1.y); u.z = f2tf32(wv1.z); u.w = f2tf32(wv1.w);
        *(uint4*)&Bs[row + 32][c4] = u;
        __syncthreads();

        if (c + 1 < nC) {
            int k0 = (c + 1) * KC;
            xv0 = *(const float4*)(ap0 + k0);
            xv1 = *(const float4*)(ap1 + k0);
            wv0 = *(const float4*)(bp0 + k0);
            wv1 = *(const float4*)(bp1 + k0);
        }

#pragma unroll
        for (int ks = 0; ks < 4; ks++) {
            int kk = ks * 8;
            uint32_t a0 = As[m0 + (lane >> 2)][kk + (lane & 3)];
            uint32_t a1 = As[m0 + (lane >> 2) + 8][kk + (lane & 3)];
            uint32_t a2 = As[m0 + (lane >> 2)][kk + (lane & 3) + 4];
            uint32_t a3 = As[m0 + (lane >> 2) + 8][kk + (lane & 3) + 4];
#pragma unroll
            for (int nt = 0; nt < 4; nt++) {
                uint32_t b0 = Bs[n0 + nt * 8 + (lane >> 2)][kk + (lane & 3)];
                uint32_t b1 = Bs[n0 + nt * 8 + (lane >> 2)][kk + (lane & 3) + 4];
                mma_tf32(acc[nt][0], acc[nt][1], acc[nt][2], acc[nt][3],
                         a0, a1, a2, a3, b0, b1);
            }
        }
        __syncthreads();
    }

#pragma unroll
    for (int nt = 0; nt < 4; nt++) {
        int r = mblk * 64 + m0 + (lane >> 2);
        int cc = nblk * 64 + n0 + nt * 8 + (lane & 3) * 2;
        float bz0 = bias[cc], bz1 = bias[cc + 1];
        float2 v0 = make_float2(acc[nt][0] + bz0, acc[nt][1] + bz1);
        float2 v1 = make_float2(acc[nt][2] + bz0, acc[nt][3] + bz1);
        if (mode == 0) {
            *(float2*)&g_enc[r * Hq + cc] = v0;
            *(float2*)&g_enc[(r + 8) * Hq + cc] = v1;
        } else {
            int tt = r >> 6, bb = r & 63;
            __stcs((float2*)&Cext[((size_t)bb * Lq + tt) * Hq + cc], v0);
            int r8 = r + 8;
            tt = r8 >> 6; bb = r8 & 63;
            __stcs((float2*)&Cext[((size_t)bb * Lq + tt) * Hq + cc], v1);
        }
    }
}

// ============ persistent LSTM: all 127 steps in one launch ============
// blocks 0..63:  layer1 executor for j0 = bid*16, runs step p (p>=0)
// blocks 64..127: layer0 executor for j0 = (bid-64)*16, runs step p+1 (<=126)
__global__ __launch_bounds__(256, 1)
void lstm_persist_kernel(const float* __restrict__ Wih0, const float* __restrict__ Whh0,
                         const float* __restrict__ bih0, const float* __restrict__ bhh0,
                         const float* __restrict__ Wih1, const float* __restrict__ Whh1,
                         const float* __restrict__ bih1, const float* __restrict__ bhh1,
                         const int* __restrict__ text) {
    __shared__ uint32_t Xs[2][64][36];
    __shared__ uint32_t Ws[2][64][36];
    __shared__ float gsm[64][68];

    const int tid = threadIdx.x;
    const int lane = tid & 31, warp = tid >> 5;
    const int bid = blockIdx.x;
    const bool isL0 = (bid >= 64);
    const int j0 = (bid & 63) * 16;
    unsigned tgt = 0;

    // zero initial states (stripe per block), then global barrier
    for (int i = bid * 256 + tid; i < Bq * Hq; i += NPB * 256) {
        g_h0[0][i] = 0.f;
        g_h1[0][i] = 0.f;
    }
    tgt += NPB; grid_sync(tgt);

    const int m0 = (warp & 3) * 16;
    const int n0 = (warp >> 2) * 32;
    const int row = tid >> 3;
    const int c4 = (tid & 7) * 4;
    const int wr0 = (row >> 4) * Hq + j0 + (row & 15);
    const int wr1 = ((row + 32) >> 4) * Hq + j0 + ((row + 32) & 15);

    const float* W1 = isL0 ? Whh0 : Wih1;
    const float* W2 = isL0 ? Wih0 : Whh1;   // layer0: only used at step 0 (X2 = enc)
    const float* b_ih = isL0 ? bih0 : bih1;
    const float* b_hh = isL0 ? bhh0 : bhh1;

    const float* wp0A = W1 + (size_t)wr0 * Hq + c4;
    const float* wp1A = W1 + (size_t)wr1 * Hq + c4;
    const float* wp0B = W2 + (size_t)wr0 * Hq + c4;
    const float* wp1B = W2 + (size_t)wr1 * Hq + c4;

    // per-thread epilogue cell ownership (iteration-invariant):
    // cell q: index = tid + 256*q -> m = idx&63, u = idx>>6, j = j0+u
    float creg[4];        // c-state lives in registers for the whole sequence
    float bsi[4], bsf[4], bsg[4], bso[4];
#pragma unroll
    for (int q = 0; q < 4; q++) {
        creg[q] = 0.f;
        int u = (tid + 256 * q) >> 6;
        int j = j0 + u;
        bsi[q] = b_ih[j] + b_hh[j];
        bsf[q] = b_ih[Hq + j] + b_hh[Hq + j];
        bsg[q] = b_ih[2 * Hq + j] + b_hh[2 * Hq + j];
        bso[q] = b_ih[3 * Hq + j] + b_hh[3 * Hq + j];
    }

    for (int p = -1; p <= 126; p++) {
        const int step = isL0 ? p + 1 : p;
        const bool active = isL0 ? (step <= 126) : (step >= 0);
        if (active) {
            const int par = step & 1;
            const float* X1;
            const float* X2 = nullptr;
            float* hout;
            bool useEmb = false;
            if (isL0) {
                X1 = g_h0[par];
                if (step == 0) X2 = g_enc; else useEmb = true;
                hout = g_h0[par ^ 1];
            } else {
                X1 = g_h0[par ^ 1];
                X2 = g_h1[par];
                hout = g_h1[par ^ 1];
            }

            float acc[4][4] = {};
            const float* xp0A = X1 + (size_t)row * Hq + c4;
            const float* xp1A = X1 + (size_t)(row + 32) * Hq + c4;
            const float* xp0B = X2 ? X2 + (size_t)row * Hq + c4 : nullptr;
            const float* xp1B = X2 ? X2 + (size_t)(row + 32) * Hq + c4 : nullptr;
            const int nC = X2 ? 64 : 32;

            float4 xv0, xv1, wv0, wv1;
            auto LDGC = [&](int c) {
                int ph = c >> 5;
                int k0 = (c & 31) * KC;
                const float* x0 = ph ? xp0B : xp0A;
                const float* x1 = ph ? xp1B : xp1A;
                const float* w0 = ph ? wp0B : wp0A;
                const float* w1 = ph ? wp1B : wp1A;
                xv0 = __ldcg((const float4*)(x0 + k0));   // h-state: bypass L1 (cross-block)
                xv1 = __ldcg((const float4*)(x1 + k0));
                wv0 = *(const float4*)(w0 + k0);          // weights: L1-cached, warm across steps
                wv1 = *(const float4*)(w1 + k0);
            };
            auto STSC = [&](int buf) {
                uint4 u;
                u.x = f2tf32(xv0.x); u.y = f2tf32(xv0.y); u.z = f2tf32(xv0.z); u.w = f2tf32(xv0.w);
                *(uint4*)&Xs[buf][row][c4] = u;
                u.x = f2tf32(xv1.x); u.y = f2tf32(xv1.y); u.z = f2tf32(xv1.z); u.w = f2tf32(xv1.w);
                *(uint4*)&Xs[buf][row + 32][c4] = u;
                u.x = f2tf32(wv0.x); u.y = f2tf32(wv0.y); u.z = f2tf32(wv0.z); u.w = f2tf32(wv0.w);
                *(uint4*)&Ws[buf][row][c4] = u;
                u.x = f2tf32(wv1.x); u.y = f2tf32(wv1.y); u.z = f2tf32(wv1.z); u.w = f2tf32(wv1.w);
                *(uint4*)&Ws[buf][row + 32][c4] = u;
            };

            LDGC(0);
            STSC(0);
            __syncthreads();
            for (int c = 0; c < nC; c++) {
                const int buf = c & 1;
                if (c + 1 < nC) LDGC(c + 1);
#pragma unroll
                for (int ks = 0; ks < 4; ks++) {
                    int kk = ks * 8;
                    uint32_t a0 = Xs[buf][m0 + (lane >> 2)][kk + (lane & 3)];
                    uint32_t a1 = Xs[buf][m0 + (lane >> 2) + 8][kk + (lane & 3)];
                    uint32_t a2 = Xs[buf][m0 + (lane >> 2)][kk + (lane & 3) + 4];
                    uint32_t a3 = Xs[buf][m0 + (lane >> 2) + 8][kk + (lane & 3) + 4];
#pragma unroll
                    for (int nt = 0; nt < 4; nt++) {
                        uint32_t b0 = Ws[buf][n0 + nt * 8 + (lane >> 2)][kk + (lane & 3)];
                        uint32_t b1 = Ws[buf][n0 + nt * 8 + (lane >> 2)][kk + (lane & 3) + 4];
                        mma_tf32(acc[nt][0], acc[nt][1], acc[nt][2], acc[nt][3],
                                 a0, a1, a2, a3, b0, b1);
                    }
                }
                if (c + 1 < nC) STSC(buf ^ 1);
                __syncthreads();
            }

            // stage gates so epilogue sees all 4 gates per (m, j)
#pragma unroll
            for (int nt = 0; nt < 4; nt++) {
                int r = m0 + (lane >> 2);
                int cc = n0 + nt * 8 + (lane & 3) * 2;
                gsm[r][cc] = acc[nt][0];
                gsm[r][cc + 1] = acc[nt][1];
                gsm[r + 8][cc] = acc[nt][2];
                gsm[r + 8][cc + 1] = acc[nt][3];
            }
            __syncthreads();

            // pointwise epilogue: 1024 cells over 256 threads (c in registers)
#pragma unroll
            for (int q = 0; q < 4; q++) {
                int cell = tid + 256 * q;
                int m = cell & 63, u = cell >> 6;
                int j = j0 + u;
                float vi = gsm[m][u]      + bsi[q];
                float vf = gsm[m][16 + u] + bsf[q];
                float vg = gsm[m][32 + u] + bsg[q];
                float vo = gsm[m][48 + u] + bso[q];
                if (useEmb) {
                    int ix = text[m * SEQLEN + step];
                    vi += Wih0[(size_t)j * Hq + ix];
                    vf += Wih0[(size_t)(Hq + j) * Hq + ix];
                    vg += Wih0[(size_t)(2 * Hq + j) * Hq + ix];
                    vo += Wih0[(size_t)(3 * Hq + j) * Hq + ix];
                }
                float ig = sigf(vi), fg = sigf(vf), gg = tanhf(vg), og = sigf(vo);
                float cn = fg * creg[q] + ig * gg;
                creg[q] = cn;
                float hv = og * tanhf(cn);
                __stcg(&hout[m * Hq + j], hv);
                if (!isL0) __stcs(&g_outs[(size_t)step * Bq * Hq + m * Hq + j], hv);
            }
            __syncthreads();   // protect gsm before next iteration reuses smem
        }
        tgt += NPB; grid_sync(tgt);
    }
}

// -------- host launch (graph-capturable: kernels only) --------
extern "C" void kernel_launch(void* const* d_in, const int* in_sizes, int n_in,
                              void* d_out, int out_size) {
    const float* audio  = (const float*)d_in[0];
    const int*   text   = (const int*)d_in[1];
    const float* W_proj = (const float*)d_in[2];
    const float* b_proj = (const float*)d_in[3];
    const float* W_ih0  = (const float*)d_in[4];
    const float* W_hh0  = (const float*)d_in[5];
    const float* b_ih0  = (const float*)d_in[6];
    const float* b_hh0  = (const float*)d_in[7];
    const float* W_ih1  = (const float*)d_in[8];
    const float* W_hh1  = (const float*)d_in[9];
    const float* b_ih1  = (const float*)d_in[10];
    const float* b_hh1  = (const float*)d_in[11];
    const float* W_out  = (const float*)d_in[12];
    const float* b_out  = (const float*)d_in[13];
    float* out = (float*)d_out;

    reset_kernel<<<1, 1>>>();
    pool_kernel<<<(Bq * DIN) / 128, 128>>>(audio);
    // audio_enc = pooled @ W_proj.T + b_proj   (M=64, N=1024, K=768)
    gemm_tf32_kernel<<<dim3(16, 1), 256>>>(0, W_proj, b_proj, nullptr, DIN);

    // entire 127-step, 2-layer LSTM in one persistent launch
    lstm_persist_kernel<<<NPB, 256>>>(W_ih0, W_hh0, b_ih0, b_hh0,
                                      W_ih1, W_hh1, b_ih1, b_hh1, text);

    // logits = outs @ W_out.T + b_out   (M = 127*64 = 8128, N=1024, K=1024)
    gemm_tf32_kernel<<<dim3(16, Lq), 256>>>(1, W_out, b_out, out, Hq);
}

// round 5
// speedup vs baseline: 3.2419x; 1.0892x over previous
#include <cuda_runtime.h>
#include <cstdint>

#define Bq 64
#define Hq 1024
#define NG 4096       // gate rows (4*Hq)
#define DIN 768
#define TAUD 500
#define Lq 127
#define SEQLEN 128
#define KC 32
#define NPB 96        // 3 groups x 32 blocks

// -------- scratch (device globals) --------
__device__ float g_pooled[Bq * DIN];
__device__ float g_enc[Bq * Hq];
__device__ float g_g0[Bq * NG];         // enc @ Wih0^T (raw gates)
__device__ float g_WT[Hq * NG];         // Wih0 transposed: [char][gate-row]
__device__ float g_h0[2][Bq * Hq];
__device__ float g_h1[2][Bq * Hq];
__device__ float g_pih[2][Bq * NG];     // partial ih gates for layer1
__device__ float g_outs[Lq * Bq * Hq];
__device__ unsigned g_bar;

__device__ __forceinline__ float sigf(float x) { return 1.0f / (1.0f + __expf(-x)); }

__device__ __forceinline__ uint32_t f2tf32(float f) {
    uint32_t u;
    asm("cvt.rna.tf32.f32 %0, %1;" : "=r"(u) : "f"(f));
    return u;
}

__device__ __forceinline__ void mma_tf32(float& c0, float& c1, float& c2, float& c3,
                                         uint32_t a0, uint32_t a1, uint32_t a2, uint32_t a3,
                                         uint32_t b0, uint32_t b1) {
    asm volatile("mma.sync.aligned.m16n8k8.row.col.f32.tf32.tf32.f32 "
                 "{%0,%1,%2,%3}, {%4,%5,%6,%7}, {%8,%9}, {%0,%1,%2,%3};"
                 : "+f"(c0), "+f"(c1), "+f"(c2), "+f"(c3)
                 : "r"(a0), "r"(a1), "r"(a2), "r"(a3), "r"(b0), "r"(b1));
}

__device__ __forceinline__ void grid_sync(unsigned target) {
    __syncthreads();
    if (threadIdx.x == 0) {
        __threadfence();
        atomicAdd(&g_bar, 1u);
        unsigned v;
        do {
            asm volatile("ld.acquire.gpu.u32 %0, [%1];" : "=r"(v) : "l"(&g_bar));
        } while (v < target);
    }
    __syncthreads();
}

__global__ void reset_kernel() { g_bar = 0; }

// -------- mean-pool audio --------
__global__ void pool_kernel(const float* __restrict__ audio) {
    int i = blockIdx.x * blockDim.x + threadIdx.x;
    int b = i / DIN, d = i % DIN;
    const float* p = audio + (size_t)b * TAUD * DIN + d;
    float s = 0.f;
#pragma unroll 5
    for (int t = 0; t < TAUD; t++) s += __ldcs(p + (size_t)t * DIN);
    g_pooled[i] = s * (1.0f / TAUD);
}

// -------- transpose Wih0 -> WT[char][gate-row] --------
__global__ void transpose_kernel(const float* __restrict__ W) {
    __shared__ float tile[32][33];
    int bx = blockIdx.x;   // char tile (0..31)
    int by = blockIdx.y;   // row tile (0..127)
    int tx = threadIdx.x, ty0 = threadIdx.y;   // 32 x 8
#pragma unroll
    for (int q = 0; q < 4; q++) {
        int ty = ty0 + q * 8;
        tile[ty][tx] = W[(size_t)(by * 32 + ty) * Hq + bx * 32 + tx];
    }
    __syncthreads();
#pragma unroll
    for (int q = 0; q < 4; q++) {
        int ty = ty0 + q * 8;
        g_WT[(size_t)(bx * 32 + ty) * NG + by * 32 + tx] = tile[tx][ty];
    }
}

// ============ tf32 NT GEMM: C = A @ W^T (+ bias) ============
// mode 0: A=g_pooled K=768  -> g_enc (stride Hq, +bias)
// mode 1: A=g_outs  K=1024 -> logits remap (+bias, streaming store)
// mode 2: A=g_enc   K=1024 -> g_g0 (stride NG, no bias)
__global__ __launch_bounds__(256, 2)
void gemm_tf32_kernel(int mode, const float* __restrict__ Bw,
                      const float* __restrict__ bias,
                      float* __restrict__ Cext, int K) {
    __shared__ uint32_t As[64][36];
    __shared__ uint32_t Bs[64][36];
    const float* A = (mode == 0) ? g_pooled : (mode == 1 ? g_outs : g_enc);

    int tid = threadIdx.x;
    int lane = tid & 31, warp = tid >> 5;
    int nblk = blockIdx.x, mblk = blockIdx.y;

    int m0 = (warp & 3) * 16;
    int n0 = (warp >> 2) * 32;
    float acc[4][4] = {};

    int row = tid >> 3;
    int c4 = (tid & 7) * 4;

    const float* ap0 = A + (size_t)(mblk * 64 + row) * K + c4;
    const float* ap1 = A + (size_t)(mblk * 64 + row + 32) * K + c4;
    const float* bp0 = Bw + (size_t)(nblk * 64 + row) * K + c4;
    const float* bp1 = Bw + (size_t)(nblk * 64 + row + 32) * K + c4;

    int nC = K / KC;
    float4 xv0 = *(const float4*)ap0;
    float4 xv1 = *(const float4*)ap1;
    float4 wv0 = *(const float4*)bp0;
    float4 wv1 = *(const float4*)bp1;

    for (int c = 0; c < nC; c++) {
        uint4 u;
        u.x = f2tf32(xv0.x); u.y = f2tf32(xv0.y); u.z = f2tf32(xv0.z); u.w = f2tf32(xv0.w);
        *(uint4*)&As[row][c4] = u;
        u.x = f2tf32(xv1.x); u.y = f2tf32(xv1.y); u.z = f2tf32(xv1.z); u.w = f2tf32(xv1.w);
        *(uint4*)&As[row + 32][c4] = u;
        u.x = f2tf32(wv0.x); u.y = f2tf32(wv0.y); u.z = f2tf32(wv0.z); u.w = f2tf32(wv0.w);
        *(uint4*)&Bs[row][c4] = u;
        u.x = f2tf32(wv1.x); u.y = f2tf32(wv1.y); u.z = f2tf32(wv1.z); u.w = f2tf32(wv1.w);
        *(uint4*)&Bs[row + 32][c4] = u;
        __syncthreads();

        if (c + 1 < nC) {
            int k0 = (c + 1) * KC;
            xv0 = *(const float4*)(ap0 + k0);
            xv1 = *(const float4*)(ap1 + k0);
            wv0 = *(const float4*)(bp0 + k0);
            wv1 = *(const float4*)(bp1 + k0);
        }

#pragma unroll
        for (int ks = 0; ks < 4; ks++) {
            int kk = ks * 8;
            uint32_t a0 = As[m0 + (lane >> 2)][kk + (lane & 3)];
            uint32_t a1 = As[m0 + (lane >> 2) + 8][kk + (lane & 3)];
            uint32_t a2 = As[m0 + (lane >> 2)][kk + (lane & 3) + 4];
            uint32_t a3 = As[m0 + (lane >> 2) + 8][kk + (lane & 3) + 4];
#pragma unroll
            for (int nt = 0; nt < 4; nt++) {
                uint32_t b0 = Bs[n0 + nt * 8 + (lane >> 2)][kk + (lane & 3)];
                uint32_t b1 = Bs[n0 + nt * 8 + (lane >> 2)][kk + (lane & 3) + 4];
                mma_tf32(acc[nt][0], acc[nt][1], acc[nt][2], acc[nt][3],
                         a0, a1, a2, a3, b0, b1);
            }
        }
        __syncthreads();
    }

#pragma unroll
    for (int nt = 0; nt < 4; nt++) {
        int r = mblk * 64 + m0 + (lane >> 2);
        int cc = nblk * 64 + n0 + nt * 8 + (lane & 3) * 2;
        float bz0 = 0.f, bz1 = 0.f;
        if (mode != 2) { bz0 = bias[cc]; bz1 = bias[cc + 1]; }
        float2 v0 = make_float2(acc[nt][0] + bz0, acc[nt][1] + bz1);
        float2 v1 = make_float2(acc[nt][2] + bz0, acc[nt][3] + bz1);
        if (mode == 0) {
            *(float2*)&g_enc[r * Hq + cc] = v0;
            *(float2*)&g_enc[(r + 8) * Hq + cc] = v1;
        } else if (mode == 2) {
            *(float2*)&g_g0[r * NG + cc] = v0;
            *(float2*)&g_g0[(r + 8) * NG + cc] = v1;
        } else {
            int tt = r >> 6, bb = r & 63;
            __stcs((float2*)&Cext[((size_t)bb * Lq + tt) * Hq + cc], v0);
            int r8 = r + 8;
            tt = r8 >> 6; bb = r8 & 63;
            __stcs((float2*)&Cext[((size_t)bb * Lq + tt) * Hq + cc], v1);
        }
    }
}

// ============ persistent 3-group LSTM pipeline ============
// 96 blocks: [0,32) A = layer0(p+1), [32,64) B = layer1(p-1) finish, [64,96) C = pih(p)
// Each block: M=64 batch x N=128 gate-rows (32 units x 4 gates), K=1024.
#define XS(b, r, c) smXs[(b) * 2304 + (r) * 36 + (c)]
#define WS(b, r, c) smWs[(b) * 4608 + (r) * 36 + (c)]
#define GS(m, n)    smG[(m) * 130 + (n)]
#define SMEM_BYTES ((2 * 2304 + 2 * 4608 + 64 * 130) * 4)

__global__ __launch_bounds__(256, 1)
void lstm3_kernel(const float* __restrict__ Whh0,
                  const float* __restrict__ bih0, const float* __restrict__ bhh0,
                  const float* __restrict__ Wih1, const float* __restrict__ Whh1,
                  const float* __restrict__ bih1, const float* __restrict__ bhh1,
                  const int* __restrict__ text) {
    extern __shared__ uint32_t smem[];
    uint32_t* smXs = smem;
    uint32_t* smWs = smem + 2 * 2304;
    float*    smG  = (float*)(smem + 2 * 2304 + 2 * 4608);

    const int tid = threadIdx.x;
    const int lane = tid & 31, warp = tid >> 5;
    const int bid = blockIdx.x;
    const int group = bid >> 5;          // 0=A, 1=B, 2=C
    const int blk = bid & 31;
    const int j0 = blk * 32;
    unsigned tgt = 0;

    // zero h1 buffers (B reads h1(-1)=0 at p=1), then sync
    for (int i = bid * 256 + tid; i < 2 * Bq * Hq; i += NPB * 256)
        g_h1[0][i] = 0.f;      // covers both [0] and [1] contiguously
    tgt += NPB; grid_sync(tgt);

    // weight matrix for this group's GEMM
    const float* Wmat = (group == 0) ? Whh0 : (group == 1 ? Whh1 : Wih1);
    // biases (combined) for epilogue-owning groups; u = lane
    float bsi = 0.f, bsf = 0.f, bsg = 0.f, bso = 0.f;
    if (group == 0) {
        int j = j0 + lane;
        bsi = bih0[j] + bhh0[j];
        bsf = bih0[Hq + j] + bhh0[Hq + j];
        bsg = bih0[2 * Hq + j] + bhh0[2 * Hq + j];
        bso = bih0[3 * Hq + j] + bhh0[3 * Hq + j];
    } else if (group == 1) {
        int j = j0 + lane;
        bsi = bih1[j] + bhh1[j];
        bsf = bih1[Hq + j] + bhh1[Hq + j];
        bsg = bih1[2 * Hq + j] + bhh1[2 * Hq + j];
        bso = bih1[3 * Hq + j] + bhh1[3 * Hq + j];
    }

    // GEMM thread-load assignments
    const int xr = tid >> 2;                  // X row 0..63
    const int xf = (tid & 3) * 2;             // 2 float4 slots
    const int wr = tid >> 1;                  // W tile row 0..127
    const int wf = (tid & 1) * 4;             // 4 float4 slots
    const int wrow = (wr >> 5) * Hq + j0 + (wr & 31);   // gate*Hq + unit
    const float* wbase = Wmat + (size_t)wrow * Hq;

    // mma warp tiles: m32 x n32 grid 2x4
    const int mw = (warp & 1) * 32;
    const int nw = (warp >> 1) * 32;

    float creg[8];
#pragma unroll
    for (int q = 0; q < 8; q++) creg[q] = 0.f;

    for (int p = -1; p <= 127; p++) {
        int s; bool active; const float* Xp = nullptr; bool doGemm = true;
        if (group == 0)      { s = p + 1; active = (s >= 0 && s <= 126); Xp = (s > 0) ? g_h0[(s - 1) & 1] : nullptr; doGemm = (s > 0); }
        else if (group == 2) { s = p;     active = (s >= 0 && s <= 126); Xp = g_h0[s & 1]; }
        else                 { s = p - 1; active = (s >= 0 && s <= 126); Xp = g_h1[(s + 1) & 1]; }

        if (active) {
            float acc[2][4][4] = {};
            if (doGemm) {
                const float* xbase = Xp;
                float4 xv[2], wv[4];
                auto LDGC = [&](int c) {
                    int k0 = c * KC;
#pragma unroll
                    for (int i = 0; i < 2; i++)
                        xv[i] = __ldcg((const float4*)(xbase + (size_t)xr * Hq + k0 + (xf + i) * 4));
#pragma unroll
                    for (int i = 0; i < 4; i++)
                        wv[i] = *(const float4*)(wbase + k0 + (wf + i) * 4);
                };
                auto STSC = [&](int buf) {
#pragma unroll
                    for (int i = 0; i < 2; i++) {
                        uint4 u;
                        u.x = f2tf32(xv[i].x); u.y = f2tf32(xv[i].y);
                        u.z = f2tf32(xv[i].z); u.w = f2tf32(xv[i].w);
                        *(uint4*)&XS(buf, xr, (xf + i) * 4) = u;
                    }
#pragma unroll
                    for (int i = 0; i < 4; i++) {
                        uint4 u;
                        u.x = f2tf32(wv[i].x); u.y = f2tf32(wv[i].y);
                        u.z = f2tf32(wv[i].z); u.w = f2tf32(wv[i].w);
                        *(uint4*)&WS(buf, wr, (wf + i) * 4) = u;
                    }
                };

                LDGC(0);
                STSC(0);
                __syncthreads();
                for (int c = 0; c < 32; c++) {
                    const int buf = c & 1;
                    if (c + 1 < 32) LDGC(c + 1);
#pragma unroll
                    for (int ks = 0; ks < 4; ks++) {
                        int kk = ks * 8;
                        uint32_t a[2][4];
#pragma unroll
                        for (int ms = 0; ms < 2; ms++) {
                            int rr = mw + ms * 16 + (lane >> 2);
                            a[ms][0] = XS(buf, rr,     kk + (lane & 3));
                            a[ms][1] = XS(buf, rr + 8, kk + (lane & 3));
                            a[ms][2] = XS(buf, rr,     kk + (lane & 3) + 4);
                            a[ms][3] = XS(buf, rr + 8, kk + (lane & 3) + 4);
                        }
#pragma unroll
                        for (int ns = 0; ns < 4; ns++) {
                            int rr = nw + ns * 8 + (lane >> 2);
                            uint32_t b0 = WS(buf, rr, kk + (lane & 3));
                            uint32_t b1 = WS(buf, rr, kk + (lane & 3) + 4);
#pragma unroll
                            for (int ms = 0; ms < 2; ms++)
                                mma_tf32(acc[ms][ns][0], acc[ms][ns][1],
                                         acc[ms][ns][2], acc[ms][ns][3],
                                         a[ms][0], a[ms][1], a[ms][2], a[ms][3], b0, b1);
                        }
                    }
                    if (c + 1 < 32) STSC(buf ^ 1);
                    __syncthreads();
                }
            }

            if (group == 2) {
                // C: store raw partial gates to g_pih[p&1], coalesced-ish float2
                float* pout = g_pih[p & 1];
#pragma unroll
                for (int ms = 0; ms < 2; ms++)
#pragma unroll
                    for (int ns = 0; ns < 4; ns++)
#pragma unroll
                        for (int hh = 0; hh < 2; hh++) {
                            int m = mw + ms * 16 + (lane >> 2) + hh * 8;
                            int r = nw + ns * 8 + (lane & 3) * 2;
                            int gn = (r >> 5) * Hq + j0 + (r & 31);
                            float2 v = make_float2(acc[ms][ns][hh * 2], acc[ms][ns][hh * 2 + 1]);
                            __stcg((float2*)&pout[(size_t)m * NG + gn], v);
                        }
            } else {
                // stage gates into smem: GS[m][r], r = gate*32 + u
#pragma unroll
                for (int ms = 0; ms < 2; ms++)
#pragma unroll
                    for (int ns = 0; ns < 4; ns++)
#pragma unroll
                        for (int hh = 0; hh < 2; hh++) {
                            int m = mw + ms * 16 + (lane >> 2) + hh * 8;
                            int r = nw + ns * 8 + (lane & 3) * 2;
                            *(float2*)&GS(m, r) =
                                make_float2(acc[ms][ns][hh * 2], acc[ms][ns][hh * 2 + 1]);
                        }
                __syncthreads();

                // epilogue: u = lane, m = warp + 8q
                const int j = j0 + lane;
                if (group == 0) {
                    float* hout = g_h0[s & 1];
#pragma unroll
                    for (int q = 0; q < 8; q++) {
                        int m = warp + 8 * q;
                        float vi = GS(m, lane)      + bsi;
                        float vf = GS(m, 32 + lane) + bsf;
                        float vg = GS(m, 64 + lane) + bsg;
                        float vo = GS(m, 96 + lane) + bso;
                        if (s == 0) {
                            const float* g0 = g_g0 + (size_t)m * NG;
                            vi += g0[j]; vf += g0[Hq + j];
                            vg += g0[2 * Hq + j]; vo += g0[3 * Hq + j];
                        } else {
                            int ix = text[m * SEQLEN + s];
                            const float* wt = g_WT + (size_t)ix * NG;
                            vi += wt[j]; vf += wt[Hq + j];
                            vg += wt[2 * Hq + j]; vo += wt[3 * Hq + j];
                        }
                        float ig = sigf(vi), fg = sigf(vf), gg = tanhf(vg), og = sigf(vo);
                        float cn = fg * creg[q] + ig * gg;
                        creg[q] = cn;
                        __stcg(&hout[m * Hq + j], og * tanhf(cn));
                    }
                } else {
                    float* hout = g_h1[s & 1];
                    const float* pin = g_pih[s & 1];   // written by C at iter p-1 = s
#pragma unroll
                    for (int q = 0; q < 8; q++) {
                        int m = warp + 8 * q;
                        const float* pm = pin + (size_t)m * NG;
                        float vi = GS(m, lane)      + bsi + __ldcg(&pm[j]);
                        float vf = GS(m, 32 + lane) + bsf + __ldcg(&pm[Hq + j]);
                        float vg = GS(m, 64 + lane) + bsg + __ldcg(&pm[2 * Hq + j]);
                        float vo = GS(m, 96 + lane) + bso + __ldcg(&pm[3 * Hq + j]);
                        float ig = sigf(vi), fg = sigf(vf), gg = tanhf(vg), og = sigf(vo);
                        float cn = fg * creg[q] + ig * gg;
                        creg[q] = cn;
                        float hv = og * tanhf(cn);
                        __stcg(&hout[m * Hq + j], hv);
                        __stcs(&g_outs[(size_t)s * Bq * Hq + m * Hq + j], hv);
                    }
                }
            }
        }
        tgt += NPB; grid_sync(tgt);
    }
}

// -------- host launch --------
extern "C" void kernel_launch(void* const* d_in, const int* in_sizes, int n_in,
                              void* d_out, int out_size) {
    const float* audio  = (const float*)d_in[0];
    const int*   text   = (const int*)d_in[1];
    const float* W_proj = (const float*)d_in[2];
    const float* b_proj = (const float*)d_in[3];
    const float* W_ih0  = (const float*)d_in[4];
    const float* W_hh0  = (const float*)d_in[5];
    const float* b_ih0  = (const float*)d_in[6];
    const float* b_hh0  = (const float*)d_in[7];
    const float* W_ih1  = (const float*)d_in[8];
    const float* W_hh1  = (const float*)d_in[9];
    const float* b_ih1  = (const float*)d_in[10];
    const float* b_hh1  = (const float*)d_in[11];
    const float* W_out  = (const float*)d_in[12];
    const float* b_out  = (const float*)d_in[13];
    float* out = (float*)d_out;

    static bool attr_set = false;
    if (!attr_set) {
        cudaFuncSetAttribute(lstm3_kernel,
                             cudaFuncAttributeMaxDynamicSharedMemorySize, SMEM_BYTES);
        attr_set = true;
    }

    reset_kernel<<<1, 1>>>();
    pool_kernel<<<(Bq * DIN) / 128, 128>>>(audio);
    transpose_kernel<<<dim3(32, 128), dim3(32, 8)>>>(W_ih0);
    // enc = pooled @ W_proj^T + b_proj
    gemm_tf32_kernel<<<dim3(16, 1), 256>>>(0, W_proj, b_proj, nullptr, DIN);
    // g0 = enc @ W_ih0^T (raw)
    gemm_tf32_kernel<<<dim3(64, 1), 256>>>(2, W_ih0, nullptr, nullptr, Hq);

    lstm3_kernel<<<NPB, 256, SMEM_BYTES>>>(W_hh0, b_ih0, b_hh0,
                                           W_ih1, W_hh1, b_ih1, b_hh1, text);

    // logits = outs @ W_out^T + b_out
    gemm_tf32_kernel<<<dim3(16, Lq), 256>>>(1, W_out, b_out, out, Hq);
}

// round 8
// speedup vs baseline: 6.5513x; 2.0208x over previous
#include <cuda_runtime.h>
#include <cuda_fp16.h>
#include <cstdint>

#define Bq 64
#define Hq 1024
#define NG 4096
#define DIN 768
#define TAUD 500
#define Lq 127
#define SEQLEN 128
#define NPB 96        // 3 groups x 32 blocks

// ---- dynamic smem layout (bytes) ----
// X bufs: 2 x (64 rows x 72 halves)  = 2 x 9216
// W bufs: 2 x (128 rows x 72 halves) = 2 x 18432
// GS:     64 x 130 floats            = 33280
#define SM_WOFF 18432
#define SM_GSOFF 55296
#define SMEM_BYTES 88576

// -------- scratch --------
__device__ float g_pooled[Bq * DIN];
__device__ float g_enc[Bq * Hq];
__device__ float g_g0[Bq * NG];          // enc @ Wih0^T (raw gates) [m][gn]
__device__ float g_WT[Hq * NG];          // Wih0^T: [char][gate-row]
__device__ __half g_Wpk[3u * 32u * 128u * 1024u];  // fp16 packed W slices, 25MB
__device__ __half g_h0f[2][Bq * Hq];     // h0 state, fp16 [m][j]
__device__ __half g_h1f[2][Bq * Hq];
__device__ float g_pih[2][Bq * NG];      // layer1 partial ih gates [m][gn]
__device__ float g_outs[Lq * Bq * Hq];
__device__ unsigned g_bar;

__device__ __forceinline__ float sigf(float x) { return 1.0f / (1.0f + __expf(-x)); }

__device__ __forceinline__ uint32_t h2_as_u32(__half2 h) {
    return *reinterpret_cast<uint32_t*>(&h);
}

__device__ __forceinline__ uint32_t f2tf32(float f) {
    uint32_t u;
    asm("cvt.rna.tf32.f32 %0, %1;" : "=r"(u) : "f"(f));
    return u;
}

// fp16 tensor mma: D(f32) += A(f16) @ B(f16)
__device__ __forceinline__ void mma16816(float& c0, float& c1, float& c2, float& c3,
                                         uint32_t a0, uint32_t a1, uint32_t a2, uint32_t a3,
                                         uint32_t b0, uint32_t b1) {
    asm volatile("mma.sync.aligned.m16n8k16.row.col.f32.f16.f16.f32 "
                 "{%0,%1,%2,%3}, {%4,%5,%6,%7}, {%8,%9}, {%0,%1,%2,%3};"
                 : "+f"(c0), "+f"(c1), "+f"(c2), "+f"(c3)
                 : "r"(a0), "r"(a1), "r"(a2), "r"(a3), "r"(b0), "r"(b1));
}

// tf32 SIMT mma (prologue/logits GEMMs)
__device__ __forceinline__ void mma_tf32(float& c0, float& c1, float& c2, float& c3,
                                         uint32_t a0, uint32_t a1, uint32_t a2, uint32_t a3,
                                         uint32_t b0, uint32_t b1) {
    asm volatile("mma.sync.aligned.m16n8k8.row.col.f32.tf32.tf32.f32 "
                 "{%0,%1,%2,%3}, {%4,%5,%6,%7}, {%8,%9}, {%0,%1,%2,%3};"
                 : "+f"(c0), "+f"(c1), "+f"(c2), "+f"(c3)
                 : "r"(a0), "r"(a1), "r"(a2), "r"(a3), "r"(b0), "r"(b1));
}

__device__ __forceinline__ void grid_sync(unsigned target) {
    __syncthreads();
    if (threadIdx.x == 0) {
        __threadfence();
        atomicAdd(&g_bar, 1u);
        unsigned v;
        do {
            asm volatile("ld.acquire.gpu.u32 %0, [%1];" : "=r"(v) : "l"(&g_bar));
        } while (v < target);
    }
    __syncthreads();
}

__global__ void reset_kernel() { g_bar = 0; }

// -------- mean-pool audio --------
__global__ void pool_kernel(const float* __restrict__ audio) {
    int i = blockIdx.x * blockDim.x + threadIdx.x;
    int b = i / DIN, d = i % DIN;
    const float* p = audio + (size_t)b * TAUD * DIN + d;
    float s = 0.f;
#pragma unroll 5
    for (int t = 0; t < TAUD; t++) s += __ldcs(p + (size_t)t * DIN);
    g_pooled[i] = s * (1.0f / TAUD);
}

// -------- transpose Wih0 -> WT[char][gate-row] --------
__global__ void transpose_kernel(const float* __restrict__ W) {
    __shared__ float tile[32][33];
    int bx = blockIdx.x, by = blockIdx.y;
    int tx = threadIdx.x, ty0 = threadIdx.y;
#pragma unroll
    for (int q = 0; q < 4; q++) {
        int ty = ty0 + q * 8;
        tile[ty][tx] = W[(size_t)(by * 32 + ty) * Hq + bx * 32 + tx];
    }
    __syncthreads();
#pragma unroll
    for (int q = 0; q < 4; q++) {
        int ty = ty0 + q * 8;
        g_WT[(size_t)(bx * 32 + ty) * NG + by * 32 + tx] = tile[tx][ty];
    }
}

// -------- pack weights to fp16 per-(grp,blk) slices: row = gate*32+unit --------
__global__ void pack_w16_kernel(const float* __restrict__ W0,
                                const float* __restrict__ W1,
                                const float* __restrict__ W2) {
    int grp = blockIdx.x >> 5, blk = blockIdx.x & 31;
    const float* W = (grp == 0) ? W0 : (grp == 1 ? W1 : W2);
    int j0 = blk * 32;
    __half* dst = g_Wpk + ((size_t)(grp * 32 + blk)) * 131072;
    for (int f4 = threadIdx.x; f4 < 32768; f4 += 256) {
        int r = f4 >> 8;                 // tile row 0..127
        int c = (f4 & 255) * 4;          // k col
        int grow = (r >> 5) * Hq + j0 + (r & 31);
        float4 v = *(const float4*)(W + (size_t)grow * Hq + c);
        uint2 o;
        o.x = h2_as_u32(__floats2half2_rn(v.x, v.y));
        o.y = h2_as_u32(__floats2half2_rn(v.z, v.w));
        *(uint2*)(dst + (size_t)r * 1024 + c) = o;
    }
}

// ============ SIMT tf32 GEMM for prologue/logits ============
__global__ __launch_bounds__(256, 2)
void gemm_tf32_kernel(int mode, const float* __restrict__ Bw,
                      const float* __restrict__ bias,
                      float* __restrict__ Cext, int K) {
    __shared__ uint32_t As[64][36];
    __shared__ uint32_t Bs[64][36];
    const float* A = (mode == 0) ? g_pooled : (mode == 1 ? g_outs : g_enc);

    int tid = threadIdx.x;
    int lane = tid & 31, warp = tid >> 5;
    int nblk = blockIdx.x, mblk = blockIdx.y;
    int m0 = (warp & 3) * 16;
    int n0 = (warp >> 2) * 32;
    float acc[4][4] = {};
    int row = tid >> 3;
    int c4 = (tid & 7) * 4;

    const float* ap0 = A + (size_t)(mblk * 64 + row) * K + c4;
    const float* ap1 = A + (size_t)(mblk * 64 + row + 32) * K + c4;
    const float* bp0 = Bw + (size_t)(nblk * 64 + row) * K + c4;
    const float* bp1 = Bw + (size_t)(nblk * 64 + row + 32) * K + c4;

    int nC = K / 32;
    float4 xv0 = *(const float4*)ap0;
    float4 xv1 = *(const float4*)ap1;
    float4 wv0 = *(const float4*)bp0;
    float4 wv1 = *(const float4*)bp1;

    for (int c = 0; c < nC; c++) {
        uint4 u;
        u.x = f2tf32(xv0.x); u.y = f2tf32(xv0.y); u.z = f2tf32(xv0.z); u.w = f2tf32(xv0.w);
        *(uint4*)&As[row][c4] = u;
        u.x = f2tf32(xv1.x); u.y = f2tf32(xv1.y); u.z = f2tf32(xv1.z); u.w = f2tf32(xv1.w);
        *(uint4*)&As[row + 32][c4] = u;
        u.x = f2tf32(wv0.x); u.y = f2tf32(wv0.y); u.z = f2tf32(wv0.z); u.w = f2tf32(wv0.w);
        *(uint4*)&Bs[row][c4] = u;
        u.x = f2tf32(wv1.x); u.y = f2tf32(wv1.y); u.z = f2tf32(wv1.z); u.w = f2tf32(wv1.w);
        *(uint4*)&Bs[row + 32][c4] = u;
        __syncthreads();

        if (c + 1 < nC) {
            int k0 = (c + 1) * 32;
            xv0 = *(const float4*)(ap0 + k0);
            xv1 = *(const float4*)(ap1 + k0);
            wv0 = *(const float4*)(bp0 + k0);
            wv1 = *(const float4*)(bp1 + k0);
        }
#pragma unroll
        for (int ks = 0; ks < 4; ks++) {
            int kk = ks * 8;
            uint32_t a0 = As[m0 + (lane >> 2)][kk + (lane & 3)];
            uint32_t a1 = As[m0 + (lane >> 2) + 8][kk + (lane & 3)];
            uint32_t a2 = As[m0 + (lane >> 2)][kk + (lane & 3) + 4];
            uint32_t a3 = As[m0 + (lane >> 2) + 8][kk + (lane & 3) + 4];
#pragma unroll
            for (int nt = 0; nt < 4; nt++) {
                uint32_t b0 = Bs[n0 + nt * 8 + (lane >> 2)][kk + (lane & 3)];
                uint32_t b1 = Bs[n0 + nt * 8 + (lane >> 2)][kk + (lane & 3) + 4];
                mma_tf32(acc[nt][0], acc[nt][1], acc[nt][2], acc[nt][3],
                         a0, a1, a2, a3, b0, b1);
            }
        }
        __syncthreads();
    }

#pragma unroll
    for (int nt = 0; nt < 4; nt++) {
        int r = mblk * 64 + m0 + (lane >> 2);
        int cc = nblk * 64 + n0 + nt * 8 + (lane & 3) * 2;
        float bz0 = 0.f, bz1 = 0.f;
        if (mode != 2) { bz0 = bias[cc]; bz1 = bias[cc + 1]; }
        float2 v0 = make_float2(acc[nt][0] + bz0, acc[nt][1] + bz1);
        float2 v1 = make_float2(acc[nt][2] + bz0, acc[nt][3] + bz1);
        if (mode == 0) {
            *(float2*)&g_enc[r * Hq + cc] = v0;
            *(float2*)&g_enc[(r + 8) * Hq + cc] = v1;
        } else if (mode == 2) {
            *(float2*)&g_g0[r * NG + cc] = v0;
            *(float2*)&g_g0[(r + 8) * NG + cc] = v1;
        } else {
            int tt = r >> 6, bb = r & 63;
            __stcs((float2*)&Cext[((size_t)bb * Lq + tt) * Hq + cc], v0);
            int r8 = r + 8;
            tt = r8 >> 6; bb = r8 & 63;
            __stcs((float2*)&Cext[((size_t)bb * Lq + tt) * Hq + cc], v1);
        }
    }
}

// ============ persistent 3-group fp16-mma LSTM pipeline ============
// 96 blocks: grp0 [0,32) layer0(p+1), grp1 [32,64) layer1(p-1), grp2 [64,96) pih(p)
// Per block: D[batch 64 x 128 gate-rows] = X[64,1024] @ Wslice[128,1024]^T,
// fp16 operands / fp32 accum. 16 K-chunks of 64.
__global__ __launch_bounds__(256, 1)
void lstm_fp16_kernel(const float* __restrict__ bih0, const float* __restrict__ bhh0,
                      const float* __restrict__ bih1, const float* __restrict__ bhh1,
                      const int* __restrict__ text) {
    extern __shared__ char smem[];
    uint32_t* S32 = (uint32_t*)smem;
    float* GSp = (float*)(smem + SM_GSOFF);

    const int tid = threadIdx.x;
    const int lane = tid & 31, warp = tid >> 5;
    const int gid = lane >> 2, tig = lane & 3;
    const int bid = blockIdx.x;
    const int group = bid >> 5;
    const int blk = bid & 31;
    const int j0 = blk * 32;
    unsigned tgt = 0;

    // zero initial fp16 h1 state (both parities)
    for (int i = bid * 256 + tid; i < 2 * Bq * Hq; i += NPB * 256) {
        g_h1f[0][i] = __float2half(0.f);
    }
    tgt += NPB; grid_sync(tgt);

    const char* wslice = (const char*)(g_Wpk + ((size_t)(group * 32 + blk)) * 131072);
    const float* b_ih = (group == 0) ? bih0 : bih1;
    const float* b_hh = (group == 0) ? bhh0 : bhh1;
    float bsi = 0.f, bsf = 0.f, bsg = 0.f, bso = 0.f;
    if (group < 2) {
        int j = j0 + lane;
        bsi = b_ih[j] + b_hh[j];
        bsf = b_ih[Hq + j] + b_hh[Hq + j];
        bsg = b_ih[2 * Hq + j] + b_hh[2 * Hq + j];
        bso = b_ih[3 * Hq + j] + b_hh[3 * Hq + j];
    }

    // loader assignments
    const int xrow = tid >> 3;         // 0..31 (+32 for i=1)
    const int xu = tid & 7;            // uint4 slot within 64-half row
    // warp tiles: m (batch) mw in {0,32}; n (gate rows) 4x32
    const int mw = (warp & 1) * 32;
    const int nw = (warp >> 1) * 32;

    float creg[8];
#pragma unroll
    for (int q = 0; q < 8; q++) creg[q] = 0.f;

    for (int p = -1; p <= 127; p++) {
        int s; bool active; bool doGemm = true; const char* Xsrc = nullptr;
        if (group == 0) {
            s = p + 1; active = (s >= 0 && s <= 126);
            doGemm = (s > 0);
            if (doGemm) Xsrc = (const char*)g_h0f[(s - 1) & 1];
        } else if (group == 1) {
            s = p - 1; active = (s >= 0 && s <= 126);
            Xsrc = active ? (const char*)g_h1f[(s + 1) & 1] : nullptr;
        } else {
            s = p; active = (s >= 0 && s <= 126);
            Xsrc = active ? (const char*)g_h0f[s & 1] : nullptr;
        }

        if (active) {
            float acc[2][4][4] = {};
            if (doGemm) {
                uint4 xv[2], wv[4];
                auto LDGC = [&](int c) {
                    int cb = c * 128;   // 64 halves = 128 bytes per row-chunk
#pragma unroll
                    for (int i = 0; i < 2; i++)
                        xv[i] = __ldcg((const uint4*)(Xsrc + (size_t)(xrow + 32 * i) * 2048 + cb + xu * 16));
#pragma unroll
                    for (int i = 0; i < 4; i++)
                        wv[i] = *(const uint4*)(wslice + (size_t)(xrow + 32 * i) * 2048 + cb + xu * 16);
                };
                auto STSC = [&](int b) {
#pragma unroll
                    for (int i = 0; i < 2; i++)
                        *(uint4*)(smem + b * 9216 + (xrow + 32 * i) * 144 + xu * 16) = xv[i];
#pragma unroll
                    for (int i = 0; i < 4; i++)
                        *(uint4*)(smem + SM_WOFF + b * 18432 + (xrow + 32 * i) * 144 + xu * 16) = wv[i];
                };

                LDGC(0);
                STSC(0);
                __syncthreads();
                for (int c = 0; c < 16; c++) {
                    const int buf = c & 1;
                    if (c + 1 < 16) LDGC(c + 1);
                    const uint32_t* X32 = S32 + buf * 2304;
                    const uint32_t* W32 = S32 + 4608 + buf * 4608;
#pragma unroll
                    for (int ks = 0; ks < 4; ks++) {
                        int kw = ks * 8;
                        uint32_t a[2][4];
#pragma unroll
                        for (int ms = 0; ms < 2; ms++) {
                            int rr = mw + ms * 16 + gid;
                            a[ms][0] = X32[rr * 36 + kw + tig];
                            a[ms][1] = X32[(rr + 8) * 36 + kw + tig];
                            a[ms][2] = X32[rr * 36 + kw + tig + 4];
                            a[ms][3] = X32[(rr + 8) * 36 + kw + tig + 4];
                        }
#pragma unroll
                        for (int nt = 0; nt < 4; nt++) {
                            int rr = nw + nt * 8 + gid;
                            uint32_t b0 = W32[rr * 36 + kw + tig];
                            uint32_t b1 = W32[rr * 36 + kw + tig + 4];
#pragma unroll
                            for (int ms = 0; ms < 2; ms++)
                                mma16816(acc[ms][nt][0], acc[ms][nt][1],
                                         acc[ms][nt][2], acc[ms][nt][3],
                                         a[ms][0], a[ms][1], a[ms][2], a[ms][3], b0, b1);
                        }
                    }
                    if (c + 1 < 16) STSC(buf ^ 1);
                    __syncthreads();
                }
            }

            // stage gates into GS[m][r]  (m batch, r = gate*32 + unit)
#pragma unroll
            for (int ms = 0; ms < 2; ms++)
#pragma unroll
                for (int nt = 0; nt < 4; nt++)
#pragma unroll
                    for (int hh = 0; hh < 2; hh++) {
                        int m = mw + ms * 16 + gid + hh * 8;
                        int r = nw + nt * 8 + tig * 2;
                        *(float2*)&GSp[m * 130 + r] =
                            make_float2(acc[ms][nt][hh * 2], acc[ms][nt][hh * 2 + 1]);
                    }
            __syncthreads();

            if (group == 2) {
                float* pout = g_pih[p & 1];
                for (int idx = tid; idx < 8192; idx += 256) {
                    int m = idx >> 7, gl = idx & 127;
                    int gn = (gl >> 5) * Hq + j0 + (gl & 31);
                    __stcg(&pout[(size_t)m * NG + gn], GSp[m * 130 + gl]);
                }
            } else {
                const int j = j0 + lane;
                __half* hpk = (group == 0) ? g_h0f[s & 1] : g_h1f[s & 1];
                const float* pin = (group == 1) ? g_pih[s & 1] : nullptr;
#pragma unroll
                for (int q = 0; q < 8; q++) {
                    int m = warp + 8 * q;
                    float vi, vf, vg, vo;
                    if (group == 0 && s == 0) {
                        const float* g0 = g_g0 + (size_t)m * NG;
                        vi = g0[j] + bsi; vf = g0[Hq + j] + bsf;
                        vg = g0[2 * Hq + j] + bsg; vo = g0[3 * Hq + j] + bso;
                    } else {
                        vi = GSp[m * 130 + lane] + bsi;
                        vf = GSp[m * 130 + 32 + lane] + bsf;
                        vg = GSp[m * 130 + 64 + lane] + bsg;
                        vo = GSp[m * 130 + 96 + lane] + bso;
                        if (group == 0) {
                            int ix = text[m * SEQLEN + s];
                            const float* wt = g_WT + (size_t)ix * NG;
                            vi += wt[j]; vf += wt[Hq + j];
                            vg += wt[2 * Hq + j]; vo += wt[3 * Hq + j];
                        } else {
                            const float* pm = pin + (size_t)m * NG;
                            vi += __ldcg(&pm[j]); vf += __ldcg(&pm[Hq + j]);
                            vg += __ldcg(&pm[2 * Hq + j]); vo += __ldcg(&pm[3 * Hq + j]);
                        }
                    }
                    float ig = sigf(vi), fg = sigf(vf), gg = tanhf(vg), og = sigf(vo);
                    float cn = fg * creg[q] + ig * gg;
                    creg[q] = cn;
                    float hv = og * tanhf(cn);
                    hpk[m * Hq + j] = __float2half(hv);
                    if (group == 1) __stcs(&g_outs[(size_t)s * Bq * Hq + m * Hq + j], hv);
                }
            }
            __syncthreads();   // protect GS before next iteration
        }
        tgt += NPB; grid_sync(tgt);
    }
}

// -------- host launch --------
extern "C" void kernel_launch(void* const* d_in, const int* in_sizes, int n_in,
                              void* d_out, int out_size) {
    const float* audio  = (const float*)d_in[0];
    const int*   text   = (const int*)d_in[1];
    const float* W_proj = (const float*)d_in[2];
    const float* b_proj = (const float*)d_in[3];
    const float* W_ih0  = (const float*)d_in[4];
    const float* W_hh0  = (const float*)d_in[5];
    const float* b_ih0  = (const float*)d_in[6];
    const float* b_hh0  = (const float*)d_in[7];
    const float* W_ih1  = (const float*)d_in[8];
    const float* W_hh1  = (const float*)d_in[9];
    const float* b_ih1  = (const float*)d_in[10];
    const float* b_hh1  = (const float*)d_in[11];
    const float* W_out  = (const float*)d_in[12];
    const float* b_out  = (const float*)d_in[13];
    float* out = (float*)d_out;

    cudaFuncSetAttribute(lstm_fp16_kernel,
                         cudaFuncAttributeMaxDynamicSharedMemorySize, SMEM_BYTES);

    reset_kernel<<<1, 1>>>();
    pool_kernel<<<(Bq * DIN) / 128, 128>>>(audio);
    transpose_kernel<<<dim3(32, 128), dim3(32, 8)>>>(W_ih0);
    // fp16 weight slices: grp0=Whh0, grp1=Whh1, grp2=Wih1
    pack_w16_kernel<<<96, 256>>>(W_hh0, W_hh1, W_ih1);
    // enc = pooled @ W_proj^T + b_proj
    gemm_tf32_kernel<<<dim3(16, 1), 256>>>(0, W_proj, b_proj, nullptr, DIN);
    // g0 = enc @ W_ih0^T (raw gates)
    gemm_tf32_kernel<<<dim3(64, 1), 256>>>(2, W_ih0, nullptr, nullptr, Hq);

    lstm_fp16_kernel<<<NPB, 256, SMEM_BYTES>>>(b_ih0, b_hh0, b_ih1, b_hh1, text);

    // logits = outs @ W_out^T + b_out
    gemm_tf32_kernel<<<dim3(16, Lq), 256>>>(1, W_out, b_out, out, Hq);
}

// round 9
// speedup vs baseline: 7.4825x; 1.1421x over previous
#include <cuda_runtime.h>
#include <cuda_fp16.h>
#include <cstdint>

#define Bq 64
#define Hq 1024
#define NG 4096
#define DIN 768
#define TAUD 500
#define Lq 127
#define SEQLEN 128
#define NPB 128       // 4 groups x 32 blocks

// ---- dynamic smem layout (bytes) ----
// X bufs: 2 x (64 rows x 72 halves)  = 2 x 9216
// W bufs: 2 x (128 rows x 72 halves) = 2 x 18432
// GS:     64 x 130 floats            = 33280
#define SM_WOFF 18432
#define SM_GSOFF 55296
#define SMEM_BYTES 88576

// -------- scratch --------
__device__ float g_pooled[Bq * DIN];
__device__ float g_enc[Bq * Hq];
__device__ float g_g0[Bq * NG];          // enc @ Wih0^T (raw gates) [m][gn]
__device__ float g_WT[Hq * NG];          // Wih0^T: [char][gate-row]
__device__ __half g_Wpk[3u * 32u * 128u * 1024u];  // fp16 packed W slices, 25MB
__device__ __half g_Wout16[Hq * Hq];     // fp16 W_out [n][k]
__device__ __half g_h0f[2][Bq * Hq];     // h0 state, fp16 [m][j]
__device__ __half g_h1f[2][Bq * Hq];
__device__ __half g_outs16[Lq * Bq * Hq];  // layer1 outputs fp16 [s][m][j]
__device__ float g_pih[2][Bq * NG];      // layer1 partial ih gates [m][gn]
__device__ unsigned g_bar;

__device__ __forceinline__ float sigf(float x) { return 1.0f / (1.0f + __expf(-x)); }

__device__ __forceinline__ uint32_t h2_as_u32(__half2 h) {
    return *reinterpret_cast<uint32_t*>(&h);
}

__device__ __forceinline__ uint32_t s2u(const void* p) {
    uint32_t a;
    asm("{ .reg .u64 t; cvta.to.shared.u64 t, %1; cvt.u32.u64 %0, t; }" : "=r"(a) : "l"(p));
    return a;
}

__device__ __forceinline__ uint32_t f2tf32(float f) {
    uint32_t u;
    asm("cvt.rna.tf32.f32 %0, %1;" : "=r"(u) : "f"(f));
    return u;
}

__device__ __forceinline__ void ldsm_x4(uint32_t& r0, uint32_t& r1, uint32_t& r2, uint32_t& r3,
                                        uint32_t addr) {
    asm volatile("ldmatrix.sync.aligned.m8n8.x4.shared.b16 {%0,%1,%2,%3}, [%4];"
                 : "=r"(r0), "=r"(r1), "=r"(r2), "=r"(r3) : "r"(addr));
}
__device__ __forceinline__ void ldsm_x2(uint32_t& r0, uint32_t& r1, uint32_t addr) {
    asm volatile("ldmatrix.sync.aligned.m8n8.x2.shared.b16 {%0,%1}, [%2];"
                 : "=r"(r0), "=r"(r1) : "r"(addr));
}

// fp16 tensor mma: D(f32) += A(f16) @ B(f16)
__device__ __forceinline__ void mma16816(float& c0, float& c1, float& c2, float& c3,
                                         uint32_t a0, uint32_t a1, uint32_t a2, uint32_t a3,
                                         uint32_t b0, uint32_t b1) {
    asm volatile("mma.sync.aligned.m16n8k16.row.col.f32.f16.f16.f32 "
                 "{%0,%1,%2,%3}, {%4,%5,%6,%7}, {%8,%9}, {%0,%1,%2,%3};"
                 : "+f"(c0), "+f"(c1), "+f"(c2), "+f"(c3)
                 : "r"(a0), "r"(a1), "r"(a2), "r"(a3), "r"(b0), "r"(b1));
}

// tf32 SIMT mma (prologue GEMMs)
__device__ __forceinline__ void mma_tf32(float& c0, float& c1, float& c2, float& c3,
                                         uint32_t a0, uint32_t a1, uint32_t a2, uint32_t a3,
                                         uint32_t b0, uint32_t b1) {
    asm volatile("mma.sync.aligned.m16n8k8.row.col.f32.tf32.tf32.f32 "
                 "{%0,%1,%2,%3}, {%4,%5,%6,%7}, {%8,%9}, {%0,%1,%2,%3};"
                 : "+f"(c0), "+f"(c1), "+f"(c2), "+f"(c3)
                 : "r"(a0), "r"(a1), "r"(a2), "r"(a3), "r"(b0), "r"(b1));
}

__device__ __forceinline__ void grid_sync(unsigned target) {
    __syncthreads();
    if (threadIdx.x == 0) {
        __threadfence();
        atomicAdd(&g_bar, 1u);
        unsigned v;
        do {
            asm volatile("ld.acquire.gpu.u32 %0, [%1];" : "=r"(v) : "l"(&g_bar));
        } while (v < target);
    }
    __syncthreads();
}

__global__ void reset_kernel() { g_bar = 0; }

// -------- mean-pool audio --------
__global__ void pool_kernel(const float* __restrict__ audio) {
    int i = blockIdx.x * blockDim.x + threadIdx.x;
    int b = i / DIN, d = i % DIN;
    const float* p = audio + (size_t)b * TAUD * DIN + d;
    float s = 0.f;
#pragma unroll 5
    for (int t = 0; t < TAUD; t++) s += __ldcs(p + (size_t)t * DIN);
    g_pooled[i] = s * (1.0f / TAUD);
}

// -------- transpose Wih0 -> WT[char][gate-row] --------
__global__ void transpose_kernel(const float* __restrict__ W) {
    __shared__ float tile[32][33];
    int bx = blockIdx.x, by = blockIdx.y;
    int tx = threadIdx.x, ty0 = threadIdx.y;
#pragma unroll
    for (int q = 0; q < 4; q++) {
        int ty = ty0 + q * 8;
        tile[ty][tx] = W[(size_t)(by * 32 + ty) * Hq + bx * 32 + tx];
    }
    __syncthreads();
#pragma unroll
    for (int q = 0; q < 4; q++) {
        int ty = ty0 + q * 8;
        g_WT[(size_t)(bx * 32 + ty) * NG + by * 32 + tx] = tile[tx][ty];
    }
}

// -------- pack weights to fp16 per-(grp,blk) slices: row = gate*32+unit --------
__global__ void pack_w16_kernel(const float* __restrict__ W0,
                                const float* __restrict__ W1,
                                const float* __restrict__ W2) {
    int grp = blockIdx.x >> 5, blk = blockIdx.x & 31;
    const float* W = (grp == 0) ? W0 : (grp == 1 ? W1 : W2);
    int j0 = blk * 32;
    __half* dst = g_Wpk + ((size_t)(grp * 32 + blk)) * 131072;
    for (int f4 = threadIdx.x; f4 < 32768; f4 += 256) {
        int r = f4 >> 8;                 // tile row 0..127
        int c = (f4 & 255) * 4;          // k col
        int grow = (r >> 5) * Hq + j0 + (r & 31);
        float4 v = *(const float4*)(W + (size_t)grow * Hq + c);
        uint2 o;
        o.x = h2_as_u32(__floats2half2_rn(v.x, v.y));
        o.y = h2_as_u32(__floats2half2_rn(v.z, v.w));
        *(uint2*)(dst + (size_t)r * 1024 + c) = o;
    }
}

// -------- pack W_out to fp16 row-major --------
__global__ void pack_wout_kernel(const float* __restrict__ W) {
    int i = blockIdx.x * blockDim.x + threadIdx.x;   // 262144 float4 quads
    float4 v = *(const float4*)(W + (size_t)i * 4);
    uint2 o;
    o.x = h2_as_u32(__floats2half2_rn(v.x, v.y));
    o.y = h2_as_u32(__floats2half2_rn(v.z, v.w));
    *(uint2*)(g_Wout16 + (size_t)i * 4) = o;
}

// ============ SIMT tf32 GEMM for prologue ============
// mode 0: A=g_pooled K=768 -> g_enc (+bias);  mode 2: A=g_enc K=1024 -> g_g0
__global__ __launch_bounds__(256, 2)
void gemm_tf32_kernel(int mode, const float* __restrict__ Bw,
                      const float* __restrict__ bias, int K) {
    __shared__ uint32_t As[64][36];
    __shared__ uint32_t Bs[64][36];
    const float* A = (mode == 0) ? g_pooled : g_enc;

    int tid = threadIdx.x;
    int lane = tid & 31, warp = tid >> 5;
    int nblk = blockIdx.x, mblk = blockIdx.y;
    int m0 = (warp & 3) * 16;
    int n0 = (warp >> 2) * 32;
    float acc[4][4] = {};
    int row = tid >> 3;
    int c4 = (tid & 7) * 4;

    const float* ap0 = A + (size_t)(mblk * 64 + row) * K + c4;
    const float* ap1 = A + (size_t)(mblk * 64 + row + 32) * K + c4;
    const float* bp0 = Bw + (size_t)(nblk * 64 + row) * K + c4;
    const float* bp1 = Bw + (size_t)(nblk * 64 + row + 32) * K + c4;

    int nC = K / 32;
    float4 xv0 = *(const float4*)ap0;
    float4 xv1 = *(const float4*)ap1;
    float4 wv0 = *(const float4*)bp0;
    float4 wv1 = *(const float4*)bp1;

    for (int c = 0; c < nC; c++) {
        uint4 u;
        u.x = f2tf32(xv0.x); u.y = f2tf32(xv0.y); u.z = f2tf32(xv0.z); u.w = f2tf32(xv0.w);
        *(uint4*)&As[row][c4] = u;
        u.x = f2tf32(xv1.x); u.y = f2tf32(xv1.y); u.z = f2tf32(xv1.z); u.w = f2tf32(xv1.w);
        *(uint4*)&As[row + 32][c4] = u;
        u.x = f2tf32(wv0.x); u.y = f2tf32(wv0.y); u.z = f2tf32(wv0.z); u.w = f2tf32(wv0.w);
        *(uint4*)&Bs[row][c4] = u;
        u.x = f2tf32(wv1.x); u.y = f2tf32(wv1.y); u.z = f2tf32(wv1.z); u.w = f2tf32(wv1.w);
        *(uint4*)&Bs[row + 32][c4] = u;
        __syncthreads();

        if (c + 1 < nC) {
            int k0 = (c + 1) * 32;
            xv0 = *(const float4*)(ap0 + k0);
            xv1 = *(const float4*)(ap1 + k0);
            wv0 = *(const float4*)(bp0 + k0);
            wv1 = *(const float4*)(bp1 + k0);
        }
#pragma unroll
        for (int ks = 0; ks < 4; ks++) {
            int kk = ks * 8;
            uint32_t a0 = As[m0 + (lane >> 2)][kk + (lane & 3)];
            uint32_t a1 = As[m0 + (lane >> 2) + 8][kk + (lane & 3)];
            uint32_t a2 = As[m0 + (lane >> 2)][kk + (lane & 3) + 4];
            uint32_t a3 = As[m0 + (lane >> 2) + 8][kk + (lane & 3) + 4];
#pragma unroll
            for (int nt = 0; nt < 4; nt++) {
                uint32_t b0 = Bs[n0 + nt * 8 + (lane >> 2)][kk + (lane & 3)];
                uint32_t b1 = Bs[n0 + nt * 8 + (lane >> 2)][kk + (lane & 3) + 4];
                mma_tf32(acc[nt][0], acc[nt][1], acc[nt][2], acc[nt][3],
                         a0, a1, a2, a3, b0, b1);
            }
        }
        __syncthreads();
    }

#pragma unroll
    for (int nt = 0; nt < 4; nt++) {
        int r = mblk * 64 + m0 + (lane >> 2);
        int cc = nblk * 64 + n0 + nt * 8 + (lane & 3) * 2;
        float bz0 = 0.f, bz1 = 0.f;
        if (mode == 0) { bz0 = bias[cc]; bz1 = bias[cc + 1]; }
        float2 v0 = make_float2(acc[nt][0] + bz0, acc[nt][1] + bz1);
        float2 v1 = make_float2(acc[nt][2] + bz0, acc[nt][3] + bz1);
        if (mode == 0) {
            *(float2*)&g_enc[r * Hq + cc] = v0;
            *(float2*)&g_enc[(r + 8) * Hq + cc] = v1;
        } else {
            *(float2*)&g_g0[r * NG + cc] = v0;
            *(float2*)&g_g0[(r + 8) * NG + cc] = v1;
        }
    }
}

// ============ persistent 4-group fp16-mma LSTM + logits pipeline ============
// grp0 [0,32):   layer0 step s=p+1
// grp1 [32,64):  layer1-hh finish, step s=p-1 (writes h1 + outs16)
// grp2 [64,96):  layer1-ih partial, step s=p
// grp3 [96,128): logits for step s=p-2 (N=32 cols/block)
__global__ __launch_bounds__(256, 1)
void lstm_fp16_kernel(const float* __restrict__ bih0, const float* __restrict__ bhh0,
                      const float* __restrict__ bih1, const float* __restrict__ bhh1,
                      const float* __restrict__ b_out,
                      const int* __restrict__ text,
                      float* __restrict__ out) {
    extern __shared__ char smem[];
    float* GSp = (float*)(smem + SM_GSOFF);
    const uint32_t sbase = s2u(smem);

    const int tid = threadIdx.x;
    const int lane = tid & 31, warp = tid >> 5;
    const int gid = lane >> 2, tig = lane & 3;
    const int bid = blockIdx.x;
    const int group = bid >> 5;
    const int blk = bid & 31;
    const int j0 = blk * 32;
    unsigned tgt = 0;

    // zero initial fp16 h1 state (both parities)
    for (int i = bid * 256 + tid; i < 2 * Bq * Hq; i += NPB * 256)
        g_h1f[0][i] = __float2half(0.f);
    tgt += NPB; grid_sync(tgt);

    const char* wslice = (group < 3)
        ? (const char*)(g_Wpk + ((size_t)(group * 32 + blk)) * 131072)
        : (const char*)(g_Wout16 + (size_t)j0 * Hq);
    const float* b_ih = (group == 0) ? bih0 : bih1;
    const float* b_hh = (group == 0) ? bhh0 : bhh1;
    float bsi = 0.f, bsf = 0.f, bsg = 0.f, bso = 0.f;
    if (group < 2) {
        int j = j0 + lane;
        bsi = b_ih[j] + b_hh[j];
        bsf = b_ih[Hq + j] + b_hh[Hq + j];
        bsg = b_ih[2 * Hq + j] + b_hh[2 * Hq + j];
        bso = b_ih[3 * Hq + j] + b_hh[3 * Hq + j];
    }

    // loader assignments
    const int xrow = tid >> 3;         // 0..31 (+32 for second X row batch)
    const int xu = tid & 7;            // uint4 slot within 64-half row-chunk
    // warp tiles
    const int mw = (warp & 1) * 32;          // batch half
    const int nw = (warp >> 1) * 32;         // main: 32 gate-rows
    const int nwD = (warp >> 1) * 8;         // grp3: 8 logit cols

    float creg[8];
#pragma unroll
    for (int q = 0; q < 8; q++) creg[q] = 0.f;

    for (int p = -1; p <= 128; p++) {
        int s; bool active; bool doGemm = true; const char* Xsrc = nullptr;
        if (group == 0) {
            s = p + 1; active = (s >= 0 && s <= 126);
            doGemm = (s > 0);
            if (doGemm) Xsrc = (const char*)g_h0f[(s - 1) & 1];
        } else if (group == 1) {
            s = p - 1; active = (s >= 0 && s <= 126);
            Xsrc = active ? (const char*)g_h1f[(s + 1) & 1] : nullptr;
        } else if (group == 2) {
            s = p; active = (s >= 0 && s <= 126);
            Xsrc = active ? (const char*)g_h0f[s & 1] : nullptr;
        } else {
            s = p - 2; active = (s >= 0 && s <= 126);
            Xsrc = active ? (const char*)(g_outs16 + (size_t)s * Bq * Hq) : nullptr;
        }

        if (active && group == 3) {
            // ---- logits: D[64 x 32] = outs16[s] @ Wout[j0:j0+32]^T ----
            float acc[2][4] = {};
            uint4 xv[2], wv;
            auto LDGD = [&](int c) {
                int cb = c * 128;
#pragma unroll
                for (int i = 0; i < 2; i++)
                    xv[i] = __ldcg((const uint4*)(Xsrc + (size_t)(xrow + 32 * i) * 2048 + cb + xu * 16));
                wv = *(const uint4*)(wslice + (size_t)xrow * 2048 + cb + xu * 16);
            };
            auto STSD = [&](int b) {
#pragma unroll
                for (int i = 0; i < 2; i++)
                    *(uint4*)(smem + b * 9216 + (xrow + 32 * i) * 144 + xu * 16) = xv[i];
                *(uint4*)(smem + SM_WOFF + b * 18432 + xrow * 144 + xu * 16) = wv;
            };
            LDGD(0);
            STSD(0);
            __syncthreads();
            for (int c = 0; c < 16; c++) {
                const int buf = c & 1;
                if (c + 1 < 16) LDGD(c + 1);
                const uint32_t xb = sbase + buf * 9216;
                const uint32_t wb = sbase + SM_WOFF + buf * 18432;
#pragma unroll
                for (int ks = 0; ks < 4; ks++) {
                    int kh = ks * 16;
                    uint32_t a[2][4], b0, b1;
#pragma unroll
                    for (int ms = 0; ms < 2; ms++) {
                        uint32_t ra = xb + (mw + ms * 16 + (lane & 15)) * 144
                                    + (kh + ((lane >> 4) << 3)) * 2;
                        ldsm_x4(a[ms][0], a[ms][1], a[ms][2], a[ms][3], ra);
                    }
                    uint32_t rb = wb + (nwD + (lane & 7)) * 144
                                + (kh + (((lane >> 3) & 1) << 3)) * 2;
                    ldsm_x2(b0, b1, rb);
#pragma unroll
                    for (int ms = 0; ms < 2; ms++)
                        mma16816(acc[ms][0], acc[ms][1], acc[ms][2], acc[ms][3],
                                 a[ms][0], a[ms][1], a[ms][2], a[ms][3], b0, b1);
                }
                if (c + 1 < 16) STSD(buf ^ 1);
                __syncthreads();
            }
            // epilogue: direct stores
            int n = j0 + nwD + tig * 2;
            float bz0 = b_out[n], bz1 = b_out[n + 1];
#pragma unroll
            for (int ms = 0; ms < 2; ms++) {
                int m = mw + ms * 16 + gid;
                __stcs((float2*)&out[((size_t)m * Lq + s) * Hq + n],
                       make_float2(acc[ms][0] + bz0, acc[ms][1] + bz1));
                __stcs((float2*)&out[((size_t)(m + 8) * Lq + s) * Hq + n],
                       make_float2(acc[ms][2] + bz0, acc[ms][3] + bz1));
            }
        } else if (active) {
            float acc[2][4][4] = {};
            if (doGemm) {
                uint4 xv[2], wv[4];
                auto LDGC = [&](int c) {
                    int cb = c * 128;
#pragma unroll
                    for (int i = 0; i < 2; i++)
                        xv[i] = __ldcg((const uint4*)(Xsrc + (size_t)(xrow + 32 * i) * 2048 + cb + xu * 16));
#pragma unroll
                    for (int i = 0; i < 4; i++)
                        wv[i] = *(const uint4*)(wslice + (size_t)(xrow + 32 * i) * 2048 + cb + xu * 16);
                };
                auto STSC = [&](int b) {
#pragma unroll
                    for (int i = 0; i < 2; i++)
                        *(uint4*)(smem + b * 9216 + (xrow + 32 * i) * 144 + xu * 16) = xv[i];
#pragma unroll
                    for (int i = 0; i < 4; i++)
                        *(uint4*)(smem + SM_WOFF + b * 18432 + (xrow + 32 * i) * 144 + xu * 16) = wv[i];
                };

                LDGC(0);
                STSC(0);
                __syncthreads();
                for (int c = 0; c < 16; c++) {
                    const int buf = c & 1;
                    if (c + 1 < 16) LDGC(c + 1);
                    const uint32_t xb = sbase + buf * 9216;
                    const uint32_t wb = sbase + SM_WOFF + buf * 18432;
#pragma unroll
                    for (int ks = 0; ks < 4; ks++) {
                        int kh = ks * 16;
                        uint32_t a[2][4], b[2][4];
#pragma unroll
                        for (int ms = 0; ms < 2; ms++) {
                            uint32_t ra = xb + (mw + ms * 16 + (lane & 15)) * 144
                                        + (kh + ((lane >> 4) << 3)) * 2;
                            ldsm_x4(a[ms][0], a[ms][1], a[ms][2], a[ms][3], ra);
                        }
#pragma unroll
                        for (int nt2 = 0; nt2 < 2; nt2++) {
                            uint32_t rb = wb + (nw + nt2 * 16 + (lane & 7) + ((lane >> 4) << 3)) * 144
                                        + (kh + (((lane >> 3) & 1) << 3)) * 2;
                            ldsm_x4(b[nt2][0], b[nt2][1], b[nt2][2], b[nt2][3], rb);
                        }
#pragma unroll
                        for (int nt = 0; nt < 4; nt++) {
                            uint32_t b0 = b[nt >> 1][(nt & 1) * 2];
                            uint32_t b1 = b[nt >> 1][(nt & 1) * 2 + 1];
#pragma unroll
                            for (int ms = 0; ms < 2; ms++)
                                mma16816(acc[ms][nt][0], acc[ms][nt][1],
                                         acc[ms][nt][2], acc[ms][nt][3],
                                         a[ms][0], a[ms][1], a[ms][2], a[ms][3], b0, b1);
                        }
                    }
                    if (c + 1 < 16) STSC(buf ^ 1);
                    __syncthreads();
                }
            }

            // stage gates into GS[m][r]  (m batch, r = gate*32 + unit)
#pragma unroll
            for (int ms = 0; ms < 2; ms++)
#pragma unroll
                for (int nt = 0; nt < 4; nt++)
#pragma unroll
                    for (int hh = 0; hh < 2; hh++) {
                        int m = mw + ms * 16 + gid + hh * 8;
                        int r = nw + nt * 8 + tig * 2;
                        *(float2*)&GSp[m * 130 + r] =
                            make_float2(acc[ms][nt][hh * 2], acc[ms][nt][hh * 2 + 1]);
                    }
            __syncthreads();

            if (group == 2) {
                float* pout = g_pih[p & 1];
                for (int idx = tid; idx < 8192; idx += 256) {
                    int m = idx >> 7, gl = idx & 127;
                    int gn = (gl >> 5) * Hq + j0 + (gl & 31);
                    __stcg(&pout[(size_t)m * NG + gn], GSp[m * 130 + gl]);
                }
            } else {
                const int j = j0 + lane;
                __half* hpk = (group == 0) ? g_h0f[s & 1] : g_h1f[s & 1];
                const float* pin = (group == 1) ? g_pih[s & 1] : nullptr;
#pragma unroll
                for (int q = 0; q < 8; q++) {
                    int m = warp + 8 * q;
                    float vi, vf, vg, vo;
                    if (group == 0 && s == 0) {
                        const float* g0 = g_g0 + (size_t)m * NG;
                        vi = g0[j] + bsi; vf = g0[Hq + j] + bsf;
                        vg = g0[2 * Hq + j] + bsg; vo = g0[3 * Hq + j] + bso;
                    } else {
                        vi = GSp[m * 130 + lane] + bsi;
                        vf = GSp[m * 130 + 32 + lane] + bsf;
                        vg = GSp[m * 130 + 64 + lane] + bsg;
                        vo = GSp[m * 130 + 96 + lane] + bso;
                        if (group == 0) {
                            int ix = text[m * SEQLEN + s];
                            const float* wt = g_WT + (size_t)ix * NG;
                            vi += wt[j]; vf += wt[Hq + j];
                            vg += wt[2 * Hq + j]; vo += wt[3 * Hq + j];
                        } else {
                            const float* pm = pin + (size_t)m * NG;
                            vi += __ldcg(&pm[j]); vf += __ldcg(&pm[Hq + j]);
                            vg += __ldcg(&pm[2 * Hq + j]); vo += __ldcg(&pm[3 * Hq + j]);
                        }
                    }
                    float ig = sigf(vi), fg = sigf(vf), gg = tanhf(vg), og = sigf(vo);
                    float cn = fg * creg[q] + ig * gg;
                    creg[q] = cn;
                    float hv = og * tanhf(cn);
                    __half hv16 = __float2half(hv);
                    hpk[m * Hq + j] = hv16;
                    if (group == 1) g_outs16[(size_t)s * Bq * Hq + m * Hq + j] = hv16;
                }
            }
            __syncthreads();   // protect GS before next iteration
        }
        tgt += NPB; grid_sync(tgt);
    }
}

// -------- host launch --------
extern "C" void kernel_launch(void* const* d_in, const int* in_sizes, int n_in,
                              void* d_out, int out_size) {
    const float* audio  = (const float*)d_in[0];
    const int*   text   = (const int*)d_in[1];
    const float* W_proj = (const float*)d_in[2];
    const float* b_proj = (const float*)d_in[3];
    const float* W_ih0  = (const float*)d_in[4];
    const float* W_hh0  = (const float*)d_in[5];
    const float* b_ih0  = (const float*)d_in[6];
    const float* b_hh0  = (const float*)d_in[7];
    const float* W_ih1  = (const float*)d_in[8];
    const float* W_hh1  = (const float*)d_in[9];
    const float* b_ih1  = (const float*)d_in[10];
    const float* b_hh1  = (const float*)d_in[11];
    const float* W_out  = (const float*)d_in[12];
    const float* b_out  = (const float*)d_in[13];
    float* out = (float*)d_out;

    cudaFuncSetAttribute(lstm_fp16_kernel,
                         cudaFuncAttributeMaxDynamicSharedMemorySize, SMEM_BYTES);

    reset_kernel<<<1, 1>>>();
    pool_kernel<<<(Bq * DIN) / 128, 128>>>(audio);
    transpose_kernel<<<dim3(32, 128), dim3(32, 8)>>>(W_ih0);
    pack_w16_kernel<<<96, 256>>>(W_hh0, W_hh1, W_ih1);
    pack_wout_kernel<<<1024, 256>>>(W_out);
    // enc = pooled @ W_proj^T + b_proj
    gemm_tf32_kernel<<<dim3(16, 1), 256>>>(0, W_proj, b_proj, DIN);
    // g0 = enc @ W_ih0^T (raw gates)
    gemm_tf32_kernel<<<dim3(64, 1), 256>>>(2, W_ih0, nullptr, Hq);

    lstm_fp16_kernel<<<NPB, 256, SMEM_BYTES>>>(b_ih0, b_hh0, b_ih1, b_hh1,
                                               b_out, text, out);
}

// round 10
// speedup vs baseline: 7.6700x; 1.0250x over previous
#include <cuda_runtime.h>
#include <cuda_fp16.h>
#include <cstdint>

#define Bq 64
#define Hq 1024
#define NG 4096
#define DIN 768
#define TAUD 500
#define Lq 127
#define SEQLEN 128
#define NPB 128       // 4 groups x 32 blocks

// ---- dynamic smem layout (bytes) ----
#define SM_WOFF 18432
#define SM_GSOFF 55296
#define SMEM_BYTES 88576

// -------- scratch --------
__device__ float g_pooled[Bq * DIN];
__device__ float g_enc[Bq * Hq];
__device__ float g_g0[Bq * NG];
__device__ float g_WT[Hq * NG];
__device__ __half g_Wpk[3u * 32u * 128u * 1024u];
__device__ __half g_Wout16[Hq * Hq];
__device__ __half g_h0f[2][Bq * Hq];
__device__ __half g_h1f[2][Bq * Hq];
__device__ __half g_outs16[Lq * Bq * Hq];
__device__ float g_pih[2][Bq * NG];
__device__ unsigned g_bar;
__device__ int g_fh0[Lq];
__device__ int g_fpih[Lq];
__device__ int g_fh1[Lq];

__device__ __forceinline__ float sigf(float x) { return 1.0f / (1.0f + __expf(-x)); }

__device__ __forceinline__ uint32_t h2_as_u32(__half2 h) {
    return *reinterpret_cast<uint32_t*>(&h);
}

__device__ __forceinline__ uint32_t s2u(const void* p) {
    uint32_t a;
    asm("{ .reg .u64 t; cvta.to.shared.u64 t, %1; cvt.u32.u64 %0, t; }" : "=r"(a) : "l"(p));
    return a;
}

__device__ __forceinline__ uint32_t f2tf32(float f) {
    uint32_t u;
    asm("cvt.rna.tf32.f32 %0, %1;" : "=r"(u) : "f"(f));
    return u;
}

__device__ __forceinline__ void ldsm_x4(uint32_t& r0, uint32_t& r1, uint32_t& r2, uint32_t& r3,
                                        uint32_t addr) {
    asm volatile("ldmatrix.sync.aligned.m8n8.x4.shared.b16 {%0,%1,%2,%3}, [%4];"
                 : "=r"(r0), "=r"(r1), "=r"(r2), "=r"(r3) : "r"(addr));
}
__device__ __forceinline__ void ldsm_x2(uint32_t& r0, uint32_t& r1, uint32_t addr) {
    asm volatile("ldmatrix.sync.aligned.m8n8.x2.shared.b16 {%0,%1}, [%2];"
                 : "=r"(r0), "=r"(r1) : "r"(addr));
}

__device__ __forceinline__ void mma16816(float& c0, float& c1, float& c2, float& c3,
                                         uint32_t a0, uint32_t a1, uint32_t a2, uint32_t a3,
                                         uint32_t b0, uint32_t b1) {
    asm volatile("mma.sync.aligned.m16n8k16.row.col.f32.f16.f16.f32 "
                 "{%0,%1,%2,%3}, {%4,%5,%6,%7}, {%8,%9}, {%0,%1,%2,%3};"
                 : "+f"(c0), "+f"(c1), "+f"(c2), "+f"(c3)
                 : "r"(a0), "r"(a1), "r"(a2), "r"(a3), "r"(b0), "r"(b1));
}

__device__ __forceinline__ void mma_tf32(float& c0, float& c1, float& c2, float& c3,
                                         uint32_t a0, uint32_t a1, uint32_t a2, uint32_t a3,
                                         uint32_t b0, uint32_t b1) {
    asm volatile("mma.sync.aligned.m16n8k8.row.col.f32.tf32.tf32.f32 "
                 "{%0,%1,%2,%3}, {%4,%5,%6,%7}, {%8,%9}, {%0,%1,%2,%3};"
                 : "+f"(c0), "+f"(c1), "+f"(c2), "+f"(c3)
                 : "r"(a0), "r"(a1), "r"(a2), "r"(a3), "r"(b0), "r"(b1));
}

// flag spin (acquire) — called by one thread, followed by __syncthreads
__device__ __forceinline__ void waitflag(const int* f, int need) {
    int v;
    do {
        asm volatile("ld.acquire.gpu.s32 %0, [%1];" : "=r"(v) : "l"(f));
    } while (v < need);
}

__device__ __forceinline__ void grid_sync(unsigned target) {
    __syncthreads();
    if (threadIdx.x == 0) {
        __threadfence();
        atomicAdd(&g_bar, 1u);
        unsigned v;
        do {
            asm volatile("ld.acquire.gpu.u32 %0, [%1];" : "=r"(v) : "l"(&g_bar));
        } while (v < target);
    }
    __syncthreads();
}

__global__ void reset_kernel() {
    int i = threadIdx.x;
    if (i < Lq) { g_fh0[i] = 0; g_fpih[i] = 0; g_fh1[i] = 0; }
    if (i == 0) g_bar = 0;
}

// -------- mean-pool audio --------
__global__ void pool_kernel(const float* __restrict__ audio) {
    int i = blockIdx.x * blockDim.x + threadIdx.x;
    int b = i / DIN, d = i % DIN;
    const float* p = audio + (size_t)b * TAUD * DIN + d;
    float s = 0.f;
#pragma unroll 5
    for (int t = 0; t < TAUD; t++) s += __ldcs(p + (size_t)t * DIN);
    g_pooled[i] = s * (1.0f / TAUD);
}

// -------- transpose Wih0 -> WT[char][gate-row] --------
__global__ void transpose_kernel(const float* __restrict__ W) {
    __shared__ float tile[32][33];
    int bx = blockIdx.x, by = blockIdx.y;
    int tx = threadIdx.x, ty0 = threadIdx.y;
#pragma unroll
    for (int q = 0; q < 4; q++) {
        int ty = ty0 + q * 8;
        tile[ty][tx] = W[(size_t)(by * 32 + ty) * Hq + bx * 32 + tx];
    }
    __syncthreads();
#pragma unroll
    for (int q = 0; q < 4; q++) {
        int ty = ty0 + q * 8;
        g_WT[(size_t)(bx * 32 + ty) * NG + by * 32 + tx] = tile[tx][ty];
    }
}

// -------- pack weights to fp16 per-(grp,blk) slices (384 blocks) --------
__global__ void pack_w16_kernel(const float* __restrict__ W0,
                                const float* __restrict__ W1,
                                const float* __restrict__ W2) {
    int id = blockIdx.x;              // 0..383
    int grp = id >> 7;
    int rem = id & 127;
    int blk = rem >> 2;
    int qtr = rem & 3;
    const float* W = (grp == 0) ? W0 : (grp == 1 ? W1 : W2);
    int j0 = blk * 32;
    __half* dst = g_Wpk + ((size_t)(grp * 32 + blk)) * 131072;
    int f4e = (qtr + 1) * 8192;
    for (int f4 = qtr * 8192 + threadIdx.x; f4 < f4e; f4 += 256) {
        int r = f4 >> 8;
        int c = (f4 & 255) * 4;
        int grow = (r >> 5) * Hq + j0 + (r & 31);
        float4 v = *(const float4*)(W + (size_t)grow * Hq + c);
        uint2 o;
        o.x = h2_as_u32(__floats2half2_rn(v.x, v.y));
        o.y = h2_as_u32(__floats2half2_rn(v.z, v.w));
        *(uint2*)(dst + (size_t)r * 1024 + c) = o;
    }
}

// -------- pack W_out to fp16 row-major --------
__global__ void pack_wout_kernel(const float* __restrict__ W) {
    int i = blockIdx.x * blockDim.x + threadIdx.x;
    float4 v = *(const float4*)(W + (size_t)i * 4);
    uint2 o;
    o.x = h2_as_u32(__floats2half2_rn(v.x, v.y));
    o.y = h2_as_u32(__floats2half2_rn(v.z, v.w));
    *(uint2*)(g_Wout16 + (size_t)i * 4) = o;
}

// ============ SIMT tf32 GEMM for prologue ============
__global__ __launch_bounds__(256, 2)
void gemm_tf32_kernel(int mode, const float* __restrict__ Bw,
                      const float* __restrict__ bias, int K) {
    __shared__ uint32_t As[64][36];
    __shared__ uint32_t Bs[64][36];
    const float* A = (mode == 0) ? g_pooled : g_enc;

    int tid = threadIdx.x;
    int lane = tid & 31, warp = tid >> 5;
    int nblk = blockIdx.x, mblk = blockIdx.y;
    int m0 = (warp & 3) * 16;
    int n0 = (warp >> 2) * 32;
    float acc[4][4] = {};
    int row = tid >> 3;
    int c4 = (tid & 7) * 4;

    const float* ap0 = A + (size_t)(mblk * 64 + row) * K + c4;
    const float* ap1 = A + (size_t)(mblk * 64 + row + 32) * K + c4;
    const float* bp0 = Bw + (size_t)(nblk * 64 + row) * K + c4;
    const float* bp1 = Bw + (size_t)(nblk * 64 + row + 32) * K + c4;

    int nC = K / 32;
    float4 xv0 = *(const float4*)ap0;
    float4 xv1 = *(const float4*)ap1;
    float4 wv0 = *(const float4*)bp0;
    float4 wv1 = *(const float4*)bp1;

    for (int c = 0; c < nC; c++) {
        uint4 u;
        u.x = f2tf32(xv0.x); u.y = f2tf32(xv0.y); u.z = f2tf32(xv0.z); u.w = f2tf32(xv0.w);
        *(uint4*)&As[row][c4] = u;
        u.x = f2tf32(xv1.x); u.y = f2tf32(xv1.y); u.z = f2tf32(xv1.z); u.w = f2tf32(xv1.w);
        *(uint4*)&As[row + 32][c4] = u;
        u.x = f2tf32(wv0.x); u.y = f2tf32(wv0.y); u.z = f2tf32(wv0.z); u.w = f2tf32(wv0.w);
        *(uint4*)&Bs[row][c4] = u;
        u.x = f2tf32(wv1.x); u.y = f2tf32(wv1.y); u.z = f2tf32(wv1.z); u.w = f2tf32(wv1.w);
        *(uint4*)&Bs[row + 32][c4] = u;
        __syncthreads();

        if (c + 1 < nC) {
            int k0 = (c + 1) * 32;
            xv0 = *(const float4*)(ap0 + k0);
            xv1 = *(const float4*)(ap1 + k0);
            wv0 = *(const float4*)(bp0 + k0);
            wv1 = *(const float4*)(bp1 + k0);
        }
#pragma unroll
        for (int ks = 0; ks < 4; ks++) {
            int kk = ks * 8;
            uint32_t a0 = As[m0 + (lane >> 2)][kk + (lane & 3)];
            uint32_t a1 = As[m0 + (lane >> 2) + 8][kk + (lane & 3)];
            uint32_t a2 = As[m0 + (lane >> 2)][kk + (lane & 3) + 4];
            uint32_t a3 = As[m0 + (lane >> 2) + 8][kk + (lane & 3) + 4];
#pragma unroll
            for (int nt = 0; nt < 4; nt++) {
                uint32_t b0 = Bs[n0 + nt * 8 + (lane >> 2)][kk + (lane & 3)];
                uint32_t b1 = Bs[n0 + nt * 8 + (lane >> 2)][kk + (lane & 3) + 4];
                mma_tf32(acc[nt][0], acc[nt][1], acc[nt][2], acc[nt][3],
                         a0, a1, a2, a3, b0, b1);
            }
        }
        __syncthreads();
    }

#pragma unroll
    for (int nt = 0; nt < 4; nt++) {
        int r = mblk * 64 + m0 + (lane >> 2);
        int cc = nblk * 64 + n0 + nt * 8 + (lane & 3) * 2;
        float bz0 = 0.f, bz1 = 0.f;
        if (mode == 0) { bz0 = bias[cc]; bz1 = bias[cc + 1]; }
        float2 v0 = make_float2(acc[nt][0] + bz0, acc[nt][1] + bz1);
        float2 v1 = make_float2(acc[nt][2] + bz0, acc[nt][3] + bz1);
        if (mode == 0) {
            *(float2*)&g_enc[r * Hq + cc] = v0;
            *(float2*)&g_enc[(r + 8) * Hq + cc] = v1;
        } else {
            *(float2*)&g_g0[r * NG + cc] = v0;
            *(float2*)&g_g0[(r + 8) * NG + cc] = v1;
        }
    }
}

// ============ persistent 4-group dataflow LSTM + logits ============
// grp0: layer0 h0(s);  grp1: layer1 finish h1(s)+outs16(s);
// grp2: pih(s) = h0(s)@Wih1^T;  grp3: logits(s) from outs16(s)
__global__ __launch_bounds__(256, 1)
void lstm_fp16_kernel(const float* __restrict__ bih0, const float* __restrict__ bhh0,
                      const float* __restrict__ bih1, const float* __restrict__ bhh1,
                      const float* __restrict__ b_out,
                      const int* __restrict__ text,
                      float* __restrict__ out) {
    extern __shared__ char smem[];
    float* GSp = (float*)(smem + SM_GSOFF);
    const uint32_t sbase = s2u(smem);

    const int tid = threadIdx.x;
    const int lane = tid & 31, warp = tid >> 5;
    const int gid = lane >> 2, tig = lane & 3;
    const int bid = blockIdx.x;
    const int group = bid >> 5;
    const int blk = bid & 31;
    const int j0 = blk * 32;

    // zero initial fp16 h1 state (both parities), then one-time barrier
    for (int i = bid * 256 + tid; i < 2 * Bq * Hq; i += NPB * 256)
        g_h1f[0][i] = __float2half(0.f);
    grid_sync(NPB);

    const char* wslice = (group < 3)
        ? (const char*)(g_Wpk + ((size_t)(group * 32 + blk)) * 131072)
        : (const char*)(g_Wout16 + (size_t)j0 * Hq);
    const float* b_ih = (group == 0) ? bih0 : bih1;
    const float* b_hh = (group == 0) ? bhh0 : bhh1;
    float bsi = 0.f, bsf = 0.f, bsg = 0.f, bso = 0.f;
    if (group < 2) {
        int j = j0 + lane;
        bsi = b_ih[j] + b_hh[j];
        bsf = b_ih[Hq + j] + b_hh[Hq + j];
        bsg = b_ih[2 * Hq + j] + b_hh[2 * Hq + j];
        bso = b_ih[3 * Hq + j] + b_hh[3 * Hq + j];
    }

    const int xrow = tid >> 3;
    const int xu = tid & 7;
    const int mw = (warp & 1) * 32;
    const int nw = (warp >> 1) * 32;
    const int nwD = (warp >> 1) * 8;

    float creg[8];
#pragma unroll
    for (int q = 0; q < 8; q++) creg[q] = 0.f;

    for (int s = 0; s <= 126; s++) {
        // ---- dataflow waits (RAW + WAR edges) ----
        if (tid == 0) {
            if (group == 0) {
                if (s >= 1) waitflag(&g_fh0[s - 1], 32);
                if (s >= 2) waitflag(&g_fpih[s - 2], 32);
            } else if (group == 2) {
                waitflag(&g_fh0[s], 32);
                if (s >= 2) waitflag(&g_fh1[s - 2], 32);
            } else if (group == 1) {
                waitflag(&g_fpih[s], 32);
                if (s >= 1) waitflag(&g_fh1[s - 1], 32);
            } else {
                waitflag(&g_fh1[s], 32);
            }
        }
        __syncthreads();

        bool doGemm = true;
        const char* Xsrc = nullptr;
        if (group == 0) {
            doGemm = (s > 0);
            if (doGemm) Xsrc = (const char*)g_h0f[(s - 1) & 1];
        } else if (group == 1) {
            Xsrc = (const char*)g_h1f[(s + 1) & 1];
        } else if (group == 2) {
            Xsrc = (const char*)g_h0f[s & 1];
        } else {
            Xsrc = (const char*)(g_outs16 + (size_t)s * Bq * Hq);
        }

        if (group == 3) {
            // ---- logits: D[64 x 32] ----
            float acc[2][4] = {};
            uint4 xv[2], wv;
            auto LDGD = [&](int c) {
                int cb = c * 128;
#pragma unroll
                for (int i = 0; i < 2; i++)
                    xv[i] = __ldcg((const uint4*)(Xsrc + (size_t)(xrow + 32 * i) * 2048 + cb + xu * 16));
                wv = *(const uint4*)(wslice + (size_t)xrow * 2048 + cb + xu * 16);
            };
            auto STSD = [&](int b) {
#pragma unroll
                for (int i = 0; i < 2; i++)
                    *(uint4*)(smem + b * 9216 + (xrow + 32 * i) * 144 + xu * 16) = xv[i];
                *(uint4*)(smem + SM_WOFF + b * 18432 + xrow * 144 + xu * 16) = wv;
            };
            LDGD(0);
            STSD(0);
            __syncthreads();
            for (int c = 0; c < 16; c++) {
                const int buf = c & 1;
                if (c + 1 < 16) LDGD(c + 1);
                const uint32_t xb = sbase + buf * 9216;
                const uint32_t wb = sbase + SM_WOFF + buf * 18432;
#pragma unroll
                for (int ks = 0; ks < 4; ks++) {
                    int kh = ks * 16;
                    uint32_t a[2][4], b0, b1;
#pragma unroll
                    for (int ms = 0; ms < 2; ms++) {
                        uint32_t ra = xb + (mw + ms * 16 + (lane & 15)) * 144
                                    + (kh + ((lane >> 4) << 3)) * 2;
                        ldsm_x4(a[ms][0], a[ms][1], a[ms][2], a[ms][3], ra);
                    }
                    uint32_t rb = wb + (nwD + (lane & 7)) * 144
                                + (kh + (((lane >> 3) & 1) << 3)) * 2;
                    ldsm_x2(b0, b1, rb);
#pragma unroll
                    for (int ms = 0; ms < 2; ms++)
                        mma16816(acc[ms][0], acc[ms][1], acc[ms][2], acc[ms][3],
                                 a[ms][0], a[ms][1], a[ms][2], a[ms][3], b0, b1);
                }
                if (c + 1 < 16) STSD(buf ^ 1);
                __syncthreads();
            }
            int n = j0 + nwD + tig * 2;
            float bz0 = b_out[n], bz1 = b_out[n + 1];
#pragma unroll
            for (int ms = 0; ms < 2; ms++) {
                int m = mw + ms * 16 + gid;
                __stcs((float2*)&out[((size_t)m * Lq + s) * Hq + n],
                       make_float2(acc[ms][0] + bz0, acc[ms][1] + bz1));
                __stcs((float2*)&out[((size_t)(m + 8) * Lq + s) * Hq + n],
                       make_float2(acc[ms][2] + bz0, acc[ms][3] + bz1));
            }
            __syncthreads();
            continue;   // no flag produced by logits group
        }

        float acc[2][4][4] = {};
        if (doGemm) {
            uint4 xv[2], wv[4];
            auto LDGC = [&](int c) {
                int cb = c * 128;
#pragma unroll
                for (int i = 0; i < 2; i++)
                    xv[i] = __ldcg((const uint4*)(Xsrc + (size_t)(xrow + 32 * i) * 2048 + cb + xu * 16));
#pragma unroll
                for (int i = 0; i < 4; i++)
                    wv[i] = *(const uint4*)(wslice + (size_t)(xrow + 32 * i) * 2048 + cb + xu * 16);
            };
            auto STSC = [&](int b) {
#pragma unroll
                for (int i = 0; i < 2; i++)
                    *(uint4*)(smem + b * 9216 + (xrow + 32 * i) * 144 + xu * 16) = xv[i];
#pragma unroll
                for (int i = 0; i < 4; i++)
                    *(uint4*)(smem + SM_WOFF + b * 18432 + (xrow + 32 * i) * 144 + xu * 16) = wv[i];
            };

            LDGC(0);
            STSC(0);
            __syncthreads();
            for (int c = 0; c < 16; c++) {
                const int buf = c & 1;
                if (c + 1 < 16) LDGC(c + 1);
                const uint32_t xb = sbase + buf * 9216;
                const uint32_t wb = sbase + SM_WOFF + buf * 18432;
#pragma unroll
                for (int ks = 0; ks < 4; ks++) {
                    int kh = ks * 16;
                    uint32_t a[2][4], b[2][4];
#pragma unroll
                    for (int ms = 0; ms < 2; ms++) {
                        uint32_t ra = xb + (mw + ms * 16 + (lane & 15)) * 144
                                    + (kh + ((lane >> 4) << 3)) * 2;
                        ldsm_x4(a[ms][0], a[ms][1], a[ms][2], a[ms][3], ra);
                    }
#pragma unroll
                    for (int nt2 = 0; nt2 < 2; nt2++) {
                        uint32_t rb = wb + (nw + nt2 * 16 + (lane & 7) + ((lane >> 4) << 3)) * 144
                                    + (kh + (((lane >> 3) & 1) << 3)) * 2;
                        ldsm_x4(b[nt2][0], b[nt2][1], b[nt2][2], b[nt2][3], rb);
                    }
#pragma unroll
                    for (int nt = 0; nt < 4; nt++) {
                        uint32_t b0 = b[nt >> 1][(nt & 1) * 2];
                        uint32_t b1 = b[nt >> 1][(nt & 1) * 2 + 1];
#pragma unroll
                        for (int ms = 0; ms < 2; ms++)
                            mma16816(acc[ms][nt][0], acc[ms][nt][1],
                                     acc[ms][nt][2], acc[ms][nt][3],
                                     a[ms][0], a[ms][1], a[ms][2], a[ms][3], b0, b1);
                    }
                }
                if (c + 1 < 16) STSC(buf ^ 1);
                __syncthreads();
            }
        }

        // stage gates into GS[m][r]
#pragma unroll
        for (int ms = 0; ms < 2; ms++)
#pragma unroll
            for (int nt = 0; nt < 4; nt++)
#pragma unroll
                for (int hh = 0; hh < 2; hh++) {
                    int m = mw + ms * 16 + gid + hh * 8;
                    int r = nw + nt * 8 + tig * 2;
                    *(float2*)&GSp[m * 130 + r] =
                        make_float2(acc[ms][nt][hh * 2], acc[ms][nt][hh * 2 + 1]);
                }
        __syncthreads();

        if (group == 2) {
            float* pout = g_pih[s & 1];
            for (int idx = tid; idx < 8192; idx += 256) {
                int m = idx >> 7, gl = idx & 127;
                int gn = (gl >> 5) * Hq + j0 + (gl & 31);
                __stcg(&pout[(size_t)m * NG + gn], GSp[m * 130 + gl]);
            }
        } else {
            const int j = j0 + lane;
            __half* hpk = (group == 0) ? g_h0f[s & 1] : g_h1f[s & 1];
            const float* pin = (group == 1) ? g_pih[s & 1] : nullptr;
#pragma unroll
            for (int q = 0; q < 8; q++) {
                int m = warp + 8 * q;
                float vi, vf, vg, vo;
                if (group == 0 && s == 0) {
                    const float* g0 = g_g0 + (size_t)m * NG;
                    vi = g0[j] + bsi; vf = g0[Hq + j] + bsf;
                    vg = g0[2 * Hq + j] + bsg; vo = g0[3 * Hq + j] + bso;
                } else {
                    vi = GSp[m * 130 + lane] + bsi;
                    vf = GSp[m * 130 + 32 + lane] + bsf;
                    vg = GSp[m * 130 + 64 + lane] + bsg;
                    vo = GSp[m * 130 + 96 + lane] + bso;
                    if (group == 0) {
                        int ix = text[m * SEQLEN + s];
                        const float* wt = g_WT + (size_t)ix * NG;
                        vi += wt[j]; vf += wt[Hq + j];
                        vg += wt[2 * Hq + j]; vo += wt[3 * Hq + j];
                    } else {
                        const float* pm = pin + (size_t)m * NG;
                        vi += __ldcg(&pm[j]); vf += __ldcg(&pm[Hq + j]);
                        vg += __ldcg(&pm[2 * Hq + j]); vo += __ldcg(&pm[3 * Hq + j]);
                    }
                }
                float ig = sigf(vi), fg = sigf(vf), gg = tanhf(vg), og = sigf(vo);
                float cn = fg * creg[q] + ig * gg;
                creg[q] = cn;
                float hv = og * tanhf(cn);
                __half hv16 = __float2half(hv);
                hpk[m * Hq + j] = hv16;
                if (group == 1) g_outs16[(size_t)s * Bq * Hq + m * Hq + j] = hv16;
            }
        }
        __syncthreads();

        // ---- publish completion flag ----
        if (tid == 0) {
            __threadfence();
            if (group == 0) atomicAdd(&g_fh0[s], 1);
            else if (group == 2) atomicAdd(&g_fpih[s], 1);
            else atomicAdd(&g_fh1[s], 1);
        }
    }
}

// -------- host launch --------
extern "C" void kernel_launch(void* const* d_in, const int* in_sizes, int n_in,
                              void* d_out, int out_size) {
    const float* audio  = (const float*)d_in[0];
    const int*   text   = (const int*)d_in[1];
    const float* W_proj = (const float*)d_in[2];
    const float* b_proj = (const float*)d_in[3];
    const float* W_ih0  = (const float*)d_in[4];
    const float* W_hh0  = (const float*)d_in[5];
    const float* b_ih0  = (const float*)d_in[6];
    const float* b_hh0  = (const float*)d_in[7];
    const float* W_ih1  = (const float*)d_in[8];
    const float* W_hh1  = (const float*)d_in[9];
    const float* b_ih1  = (const float*)d_in[10];
    const float* b_hh1  = (const float*)d_in[11];
    const float* W_out  = (const float*)d_in[12];
    const float* b_out  = (const float*)d_in[13];
    float* out = (float*)d_out;

    cudaFuncSetAttribute(lstm_fp16_kernel,
                         cudaFuncAttributeMaxDynamicSharedMemorySize, SMEM_BYTES);

    reset_kernel<<<1, 128>>>();
    pool_kernel<<<(Bq * DIN) / 128, 128>>>(audio);
    transpose_kernel<<<dim3(32, 128), dim3(32, 8)>>>(W_ih0);
    pack_w16_kernel<<<384, 256>>>(W_hh0, W_hh1, W_ih1);
    pack_wout_kernel<<<1024, 256>>>(W_out);
    gemm_tf32_kernel<<<dim3(16, 1), 256>>>(0, W_proj, b_proj, DIN);
    gemm_tf32_kernel<<<dim3(64, 1), 256>>>(2, W_ih0, nullptr, Hq);

    lstm_fp16_kernel<<<NPB, 256, SMEM_BYTES>>>(b_ih0, b_hh0, b_ih1, b_hh1,
                                               b_out, text, out);
}

// round 11
// speedup vs baseline: 7.7760x; 1.0138x over previous
#include <cuda_runtime.h>
#include <cuda_fp16.h>
#include <cstdint>

#define Bq 64
#define Hq 1024
#define NG 4096
#define DIN 768
#define TAUD 500
#define Lq 127
#define SEQLEN 128
#define NPB 128       // 4 groups x 32 blocks

// ---- dynamic smem layout (bytes) ----
#define SM_WOFF 18432
#define SM_GSOFF 55296
#define SMEM_BYTES 88576

// -------- scratch --------
__device__ float g_pooled[Bq * DIN];
__device__ __half g_enc16[Bq * Hq];
__device__ float g_WT[Hq * NG];
__device__ __half g_Wpk[4u * 32u * 128u * 1024u];   // Whh0, Whh1, Wih1, Wih0
__device__ __half g_Wout16[Hq * Hq];
__device__ __half g_h0f[2][Bq * Hq];
__device__ __half g_h1f[2][Bq * Hq];
__device__ __half g_outs16[Lq * Bq * Hq];
__device__ float g_pih[2][Bq * NG];
__device__ unsigned g_bar;
__device__ int g_fh0[Lq];
__device__ int g_fpih[Lq];
__device__ int g_fh1[Lq];

__device__ __forceinline__ float sigf(float x) { return 1.0f / (1.0f + __expf(-x)); }

__device__ __forceinline__ uint32_t h2_as_u32(__half2 h) {
    return *reinterpret_cast<uint32_t*>(&h);
}

__device__ __forceinline__ uint32_t s2u(const void* p) {
    uint32_t a;
    asm("{ .reg .u64 t; cvta.to.shared.u64 t, %1; cvt.u32.u64 %0, t; }" : "=r"(a) : "l"(p));
    return a;
}

__device__ __forceinline__ uint32_t f2tf32(float f) {
    uint32_t u;
    asm("cvt.rna.tf32.f32 %0, %1;" : "=r"(u) : "f"(f));
    return u;
}

__device__ __forceinline__ void ldsm_x4(uint32_t& r0, uint32_t& r1, uint32_t& r2, uint32_t& r3,
                                        uint32_t addr) {
    asm volatile("ldmatrix.sync.aligned.m8n8.x4.shared.b16 {%0,%1,%2,%3}, [%4];"
                 : "=r"(r0), "=r"(r1), "=r"(r2), "=r"(r3) : "r"(addr));
}
__device__ __forceinline__ void ldsm_x2(uint32_t& r0, uint32_t& r1, uint32_t addr) {
    asm volatile("ldmatrix.sync.aligned.m8n8.x2.shared.b16 {%0,%1}, [%2];"
                 : "=r"(r0), "=r"(r1) : "r"(addr));
}

// fp16 mma with fp16 accumulators (packed half2 x2)
__device__ __forceinline__ void mma16816h(uint32_t& d0, uint32_t& d1,
                                          uint32_t a0, uint32_t a1, uint32_t a2, uint32_t a3,
                                          uint32_t b0, uint32_t b1) {
    asm volatile("mma.sync.aligned.m16n8k16.row.col.f16.f16.f16.f16 "
                 "{%0,%1}, {%2,%3,%4,%5}, {%6,%7}, {%0,%1};"
                 : "+r"(d0), "+r"(d1)
                 : "r"(a0), "r"(a1), "r"(a2), "r"(a3), "r"(b0), "r"(b1));
}

// promote packed f16 pair into 4 f32 accumulators
__device__ __forceinline__ void promo4(float* a4, uint32_t h0, uint32_t h1) {
    float2 lo = __half22float2(*reinterpret_cast<__half2*>(&h0));
    float2 hi = __half22float2(*reinterpret_cast<__half2*>(&h1));
    a4[0] += lo.x; a4[1] += lo.y; a4[2] += hi.x; a4[3] += hi.y;
}

// tf32 SIMT mma (prologue GEMM)
__device__ __forceinline__ void mma_tf32(float& c0, float& c1, float& c2, float& c3,
                                         uint32_t a0, uint32_t a1, uint32_t a2, uint32_t a3,
                                         uint32_t b0, uint32_t b1) {
    asm volatile("mma.sync.aligned.m16n8k8.row.col.f32.tf32.tf32.f32 "
                 "{%0,%1,%2,%3}, {%4,%5,%6,%7}, {%8,%9}, {%0,%1,%2,%3};"
                 : "+f"(c0), "+f"(c1), "+f"(c2), "+f"(c3)
                 : "r"(a0), "r"(a1), "r"(a2), "r"(a3), "r"(b0), "r"(b1));
}

__device__ __forceinline__ void waitflag(const int* f, int need) {
    int v;
    do {
        asm volatile("ld.acquire.gpu.s32 %0, [%1];" : "=r"(v) : "l"(f));
    } while (v < need);
}

__device__ __forceinline__ void grid_sync(unsigned target) {
    __syncthreads();
    if (threadIdx.x == 0) {
        __threadfence();
        atomicAdd(&g_bar, 1u);
        unsigned v;
        do {
            asm volatile("ld.acquire.gpu.u32 %0, [%1];" : "=r"(v) : "l"(&g_bar));
        } while (v < target);
    }
    __syncthreads();
}

__global__ void reset_kernel() {
    int i = threadIdx.x;
    if (i < Lq) { g_fh0[i] = 0; g_fpih[i] = 0; g_fh1[i] = 0; }
    if (i == 0) g_bar = 0;
}

// -------- mean-pool audio --------
__global__ void pool_kernel(const float* __restrict__ audio) {
    int i = blockIdx.x * blockDim.x + threadIdx.x;
    int b = i / DIN, d = i % DIN;
    const float* p = audio + (size_t)b * TAUD * DIN + d;
    float s = 0.f;
#pragma unroll 5
    for (int t = 0; t < TAUD; t++) s += __ldcs(p + (size_t)t * DIN);
    g_pooled[i] = s * (1.0f / TAUD);
}

// -------- transpose Wih0 -> WT[char][gate-row] --------
__global__ void transpose_kernel(const float* __restrict__ W) {
    __shared__ float tile[32][33];
    int bx = blockIdx.x, by = blockIdx.y;
    int tx = threadIdx.x, ty0 = threadIdx.y;
#pragma unroll
    for (int q = 0; q < 4; q++) {
        int ty = ty0 + q * 8;
        tile[ty][tx] = W[(size_t)(by * 32 + ty) * Hq + bx * 32 + tx];
    }
    __syncthreads();
#pragma unroll
    for (int q = 0; q < 4; q++) {
        int ty = ty0 + q * 8;
        g_WT[(size_t)(bx * 32 + ty) * NG + by * 32 + tx] = tile[tx][ty];
    }
}

// -------- pack weights to fp16 per-(grp,blk) slices (512 blocks, 4 sets) --------
__global__ void pack_w16_kernel(const float* __restrict__ W0,
                                const float* __restrict__ W1,
                                const float* __restrict__ W2,
                                const float* __restrict__ W3) {
    int id = blockIdx.x;              // 0..511
    int grp = id >> 7;
    int rem = id & 127;
    int blk = rem >> 2;
    int qtr = rem & 3;
    const float* W = (grp == 0) ? W0 : (grp == 1 ? W1 : (grp == 2 ? W2 : W3));
    int j0 = blk * 32;
    __half* dst = g_Wpk + ((size_t)(grp * 32 + blk)) * 131072;
    int f4e = (qtr + 1) * 8192;
    for (int f4 = qtr * 8192 + threadIdx.x; f4 < f4e; f4 += 256) {
        int r = f4 >> 8;
        int c = (f4 & 255) * 4;
        int grow = (r >> 5) * Hq + j0 + (r & 31);
        float4 v = *(const float4*)(W + (size_t)grow * Hq + c);
        uint2 o;
        o.x = h2_as_u32(__floats2half2_rn(v.x, v.y));
        o.y = h2_as_u32(__floats2half2_rn(v.z, v.w));
        *(uint2*)(dst + (size_t)r * 1024 + c) = o;
    }
}

// -------- pack W_out to fp16 row-major --------
__global__ void pack_wout_kernel(const float* __restrict__ W) {
    int i = blockIdx.x * blockDim.x + threadIdx.x;
    float4 v = *(const float4*)(W + (size_t)i * 4);
    uint2 o;
    o.x = h2_as_u32(__floats2half2_rn(v.x, v.y));
    o.y = h2_as_u32(__floats2half2_rn(v.z, v.w));
    *(uint2*)(g_Wout16 + (size_t)i * 4) = o;
}

// ============ SIMT tf32 GEMM: enc = pooled @ W_proj^T + b -> fp16 [m][k] ============
__global__ __launch_bounds__(256, 2)
void gemm_enc_kernel(const float* __restrict__ Bw,
                     const float* __restrict__ bias, int K) {
    __shared__ uint32_t As[64][36];
    __shared__ uint32_t Bs[64][36];
    const float* A = g_pooled;

    int tid = threadIdx.x;
    int lane = tid & 31, warp = tid >> 5;
    int nblk = blockIdx.x;
    int m0 = (warp & 3) * 16;
    int n0 = (warp >> 2) * 32;
    float acc[4][4] = {};
    int row = tid >> 3;
    int c4 = (tid & 7) * 4;

    const float* ap0 = A + (size_t)row * K + c4;
    const float* ap1 = A + (size_t)(row + 32) * K + c4;
    const float* bp0 = Bw + (size_t)(nblk * 64 + row) * K + c4;
    const float* bp1 = Bw + (size_t)(nblk * 64 + row + 32) * K + c4;

    int nC = K / 32;
    float4 xv0 = *(const float4*)ap0;
    float4 xv1 = *(const float4*)ap1;
    float4 wv0 = *(const float4*)bp0;
    float4 wv1 = *(const float4*)bp1;

    for (int c = 0; c < nC; c++) {
        uint4 u;
        u.x = f2tf32(xv0.x); u.y = f2tf32(xv0.y); u.z = f2tf32(xv0.z); u.w = f2tf32(xv0.w);
        *(uint4*)&As[row][c4] = u;
        u.x = f2tf32(xv1.x); u.y = f2tf32(xv1.y); u.z = f2tf32(xv1.z); u.w = f2tf32(xv1.w);
        *(uint4*)&As[row + 32][c4] = u;
        u.x = f2tf32(wv0.x); u.y = f2tf32(wv0.y); u.z = f2tf32(wv0.z); u.w = f2tf32(wv0.w);
        *(uint4*)&Bs[row][c4] = u;
        u.x = f2tf32(wv1.x); u.y = f2tf32(wv1.y); u.z = f2tf32(wv1.z); u.w = f2tf32(wv1.w);
        *(uint4*)&Bs[row + 32][c4] = u;
        __syncthreads();

        if (c + 1 < nC) {
            int k0 = (c + 1) * 32;
            xv0 = *(const float4*)(ap0 + k0);
            xv1 = *(const float4*)(ap1 + k0);
            wv0 = *(const float4*)(bp0 + k0);
            wv1 = *(const float4*)(bp1 + k0);
        }
#pragma unroll
        for (int ks = 0; ks < 4; ks++) {
            int kk = ks * 8;
            uint32_t a0 = As[m0 + (lane >> 2)][kk + (lane & 3)];
            uint32_t a1 = As[m0 + (lane >> 2) + 8][kk + (lane & 3)];
            uint32_t a2 = As[m0 + (lane >> 2)][kk + (lane & 3) + 4];
            uint32_t a3 = As[m0 + (lane >> 2) + 8][kk + (lane & 3) + 4];
#pragma unroll
            for (int nt = 0; nt < 4; nt++) {
                uint32_t b0 = Bs[n0 + nt * 8 + (lane >> 2)][kk + (lane & 3)];
                uint32_t b1 = Bs[n0 + nt * 8 + (lane >> 2)][kk + (lane & 3) + 4];
                mma_tf32(acc[nt][0], acc[nt][1], acc[nt][2], acc[nt][3],
                         a0, a1, a2, a3, b0, b1);
            }
        }
        __syncthreads();
    }

#pragma unroll
    for (int nt = 0; nt < 4; nt++) {
        int r = m0 + (lane >> 2);
        int cc = nblk * 64 + n0 + nt * 8 + (lane & 3) * 2;
        float bz0 = bias[cc], bz1 = bias[cc + 1];
        *(uint32_t*)&g_enc16[r * Hq + cc] =
            h2_as_u32(__floats2half2_rn(acc[nt][0] + bz0, acc[nt][1] + bz1));
        *(uint32_t*)&g_enc16[(r + 8) * Hq + cc] =
            h2_as_u32(__floats2half2_rn(acc[nt][2] + bz0, acc[nt][3] + bz1));
    }
}

// ============ persistent 4-group dataflow LSTM + logits ============
__global__ __launch_bounds__(256, 1)
void lstm_fp16_kernel(const float* __restrict__ bih0, const float* __restrict__ bhh0,
                      const float* __restrict__ bih1, const float* __restrict__ bhh1,
                      const float* __restrict__ b_out,
                      const int* __restrict__ text,
                      float* __restrict__ out) {
    extern __shared__ char smem[];
    float* GSp = (float*)(smem + SM_GSOFF);
    const uint32_t sbase = s2u(smem);

    const int tid = threadIdx.x;
    const int lane = tid & 31, warp = tid >> 5;
    const int gid = lane >> 2, tig = lane & 3;
    const int bid = blockIdx.x;
    const int group = bid >> 5;
    const int blk = bid & 31;
    const int j0 = blk * 32;

    for (int i = bid * 256 + tid; i < 2 * Bq * Hq; i += NPB * 256)
        g_h1f[0][i] = __float2half(0.f);
    grid_sync(NPB);

    const char* wslice = (group < 3)
        ? (const char*)(g_Wpk + ((size_t)(group * 32 + blk)) * 131072)
        : (const char*)(g_Wout16 + (size_t)j0 * Hq);
    const char* wih0slice = (const char*)(g_Wpk + ((size_t)(3 * 32 + blk)) * 131072);
    const float* b_ih = (group == 0) ? bih0 : bih1;
    const float* b_hh = (group == 0) ? bhh0 : bhh1;
    float bsi = 0.f, bsf = 0.f, bsg = 0.f, bso = 0.f;
    if (group < 2) {
        int j = j0 + lane;
        bsi = b_ih[j] + b_hh[j];
        bsf = b_ih[Hq + j] + b_hh[Hq + j];
        bsg = b_ih[2 * Hq + j] + b_hh[2 * Hq + j];
        bso = b_ih[3 * Hq + j] + b_hh[3 * Hq + j];
    }

    const int xrow = tid >> 3;
    const int xu = tid & 7;
    const int mw = (warp & 1) * 32;
    const int nw = (warp >> 1) * 32;
    const int nwD = (warp >> 1) * 8;

    float creg[8];
#pragma unroll
    for (int q = 0; q < 8; q++) creg[q] = 0.f;

    for (int s = 0; s <= 126; s++) {
        // ---- dataflow waits (RAW + WAR edges) ----
        if (tid == 0) {
            if (group == 0) {
                if (s >= 1) waitflag(&g_fh0[s - 1], 32);
                if (s >= 2) waitflag(&g_fpih[s - 2], 32);
            } else if (group == 2) {
                waitflag(&g_fh0[s], 32);
                if (s >= 2) waitflag(&g_fh1[s - 2], 32);
            } else if (group == 1) {
                waitflag(&g_fpih[s], 32);
                if (s >= 1) waitflag(&g_fh1[s - 1], 32);
            } else {
                waitflag(&g_fh1[s], 32);
            }
        }
        __syncthreads();

        const char* Xsrc;
        const char* wsl = wslice;
        if (group == 0) {
            if (s == 0) { Xsrc = (const char*)g_enc16; wsl = wih0slice; }
            else Xsrc = (const char*)g_h0f[(s - 1) & 1];
        } else if (group == 1) {
            Xsrc = (const char*)g_h1f[(s + 1) & 1];
        } else if (group == 2) {
            Xsrc = (const char*)g_h0f[s & 1];
        } else {
            Xsrc = (const char*)(g_outs16 + (size_t)s * Bq * Hq);
        }

        if (group == 3) {
            // ---- logits: D[64 x 32] ----
            float acc[2][4] = {};
            uint4 xv[2], wv;
            auto LDGD = [&](int c) {
                int cb = c * 128;
#pragma unroll
                for (int i = 0; i < 2; i++)
                    xv[i] = __ldcg((const uint4*)(Xsrc + (size_t)(xrow + 32 * i) * 2048 + cb + xu * 16));
                wv = *(const uint4*)(wsl + (size_t)xrow * 2048 + cb + xu * 16);
            };
            auto STSD = [&](int b) {
#pragma unroll
                for (int i = 0; i < 2; i++)
                    *(uint4*)(smem + b * 9216 + (xrow + 32 * i) * 144 + xu * 16) = xv[i];
                *(uint4*)(smem + SM_WOFF + b * 18432 + xrow * 144 + xu * 16) = wv;
            };
            LDGD(0);
            STSD(0);
            __syncthreads();
            for (int c = 0; c < 16; c++) {
                const int buf = c & 1;
                if (c + 1 < 16) LDGD(c + 1);
                const uint32_t xb = sbase + buf * 9216;
                const uint32_t wb = sbase + SM_WOFF + buf * 18432;
                uint32_t hacc[2][2] = {};
#pragma unroll
                for (int ks = 0; ks < 4; ks++) {
                    int kh = ks * 16;
                    uint32_t a[2][4], b0, b1;
#pragma unroll
                    for (int ms = 0; ms < 2; ms++) {
                        uint32_t ra = xb + (mw + ms * 16 + (lane & 15)) * 144
                                    + (kh + ((lane >> 4) << 3)) * 2;
                        ldsm_x4(a[ms][0], a[ms][1], a[ms][2], a[ms][3], ra);
                    }
                    uint32_t rb = wb + (nwD + (lane & 7)) * 144
                                + (kh + (((lane >> 3) & 1) << 3)) * 2;
                    ldsm_x2(b0, b1, rb);
#pragma unroll
                    for (int ms = 0; ms < 2; ms++)
                        mma16816h(hacc[ms][0], hacc[ms][1],
                                  a[ms][0], a[ms][1], a[ms][2], a[ms][3], b0, b1);
                }
#pragma unroll
                for (int ms = 0; ms < 2; ms++)
                    promo4(acc[ms], hacc[ms][0], hacc[ms][1]);
                if (c + 1 < 16) STSD(buf ^ 1);
                __syncthreads();
            }
            int n = j0 + nwD + tig * 2;
            float bz0 = b_out[n], bz1 = b_out[n + 1];
#pragma unroll
            for (int ms = 0; ms < 2; ms++) {
                int m = mw + ms * 16 + gid;
                __stcs((float2*)&out[((size_t)m * Lq + s) * Hq + n],
                       make_float2(acc[ms][0] + bz0, acc[ms][1] + bz1));
                __stcs((float2*)&out[((size_t)(m + 8) * Lq + s) * Hq + n],
                       make_float2(acc[ms][2] + bz0, acc[ms][3] + bz1));
            }
            __syncthreads();
            continue;
        }

        float acc[2][4][4] = {};
        {
            uint4 xv[2], wv[4];
            auto LDGC = [&](int c) {
                int cb = c * 128;
#pragma unroll
                for (int i = 0; i < 2; i++)
                    xv[i] = __ldcg((const uint4*)(Xsrc + (size_t)(xrow + 32 * i) * 2048 + cb + xu * 16));
#pragma unroll
                for (int i = 0; i < 4; i++)
                    wv[i] = *(const uint4*)(wsl + (size_t)(xrow + 32 * i) * 2048 + cb + xu * 16);
            };
            auto STSC = [&](int b) {
#pragma unroll
                for (int i = 0; i < 2; i++)
                    *(uint4*)(smem + b * 9216 + (xrow + 32 * i) * 144 + xu * 16) = xv[i];
#pragma unroll
                for (int i = 0; i < 4; i++)
                    *(uint4*)(smem + SM_WOFF + b * 18432 + (xrow + 32 * i) * 144 + xu * 16) = wv[i];
            };

            LDGC(0);
            STSC(0);
            __syncthreads();
            for (int c = 0; c < 16; c++) {
                const int buf = c & 1;
                if (c + 1 < 16) LDGC(c + 1);
                const uint32_t xb = sbase + buf * 9216;
                const uint32_t wb = sbase + SM_WOFF + buf * 18432;
                uint32_t hacc[2][4][2] = {};
#pragma unroll
                for (int ks = 0; ks < 4; ks++) {
                    int kh = ks * 16;
                    uint32_t a[2][4], b[2][4];
#pragma unroll
                    for (int ms = 0; ms < 2; ms++) {
                        uint32_t ra = xb + (mw + ms * 16 + (lane & 15)) * 144
                                    + (kh + ((lane >> 4) << 3)) * 2;
                        ldsm_x4(a[ms][0], a[ms][1], a[ms][2], a[ms][3], ra);
                    }
#pragma unroll
                    for (int nt2 = 0; nt2 < 2; nt2++) {
                        uint32_t rb = wb + (nw + nt2 * 16 + (lane & 7) + ((lane >> 4) << 3)) * 144
                                    + (kh + (((lane >> 3) & 1) << 3)) * 2;
                        ldsm_x4(b[nt2][0], b[nt2][1], b[nt2][2], b[nt2][3], rb);
                    }
#pragma unroll
                    for (int nt = 0; nt < 4; nt++) {
                        uint32_t b0 = b[nt >> 1][(nt & 1) * 2];
                        uint32_t b1 = b[nt >> 1][(nt & 1) * 2 + 1];
#pragma unroll
                        for (int ms = 0; ms < 2; ms++)
                            mma16816h(hacc[ms][nt][0], hacc[ms][nt][1],
                                      a[ms][0], a[ms][1], a[ms][2], a[ms][3], b0, b1);
                    }
                }
#pragma unroll
                for (int ms = 0; ms < 2; ms++)
#pragma unroll
                    for (int nt = 0; nt < 4; nt++)
                        promo4(acc[ms][nt], hacc[ms][nt][0], hacc[ms][nt][1]);
                if (c + 1 < 16) STSC(buf ^ 1);
                __syncthreads();
            }
        }

        // stage gates into GS[m][r]
#pragma unroll
        for (int ms = 0; ms < 2; ms++)
#pragma unroll
            for (int nt = 0; nt < 4; nt++)
#pragma unroll
                for (int hh = 0; hh < 2; hh++) {
                    int m = mw + ms * 16 + gid + hh * 8;
                    int r = nw + nt * 8 + tig * 2;
                    *(float2*)&GSp[m * 130 + r] =
                        make_float2(acc[ms][nt][hh * 2], acc[ms][nt][hh * 2 + 1]);
                }
        __syncthreads();

        if (group == 2) {
            float* pout = g_pih[s & 1];
            for (int idx = tid; idx < 8192; idx += 256) {
                int m = idx >> 7, gl = idx & 127;
                int gn = (gl >> 5) * Hq + j0 + (gl & 31);
                __stcg(&pout[(size_t)m * NG + gn], GSp[m * 130 + gl]);
            }
        } else {
            const int j = j0 + lane;
            __half* hpk = (group == 0) ? g_h0f[s & 1] : g_h1f[s & 1];
            const float* pin = (group == 1) ? g_pih[s & 1] : nullptr;
#pragma unroll
            for (int q = 0; q < 8; q++) {
                int m = warp + 8 * q;
                float vi = GSp[m * 130 + lane] + bsi;
                float vf = GSp[m * 130 + 32 + lane] + bsf;
                float vg = GSp[m * 130 + 64 + lane] + bsg;
                float vo = GSp[m * 130 + 96 + lane] + bso;
                if (group == 0) {
                    if (s > 0) {
                        int ix = text[m * SEQLEN + s];
                        const float* wt = g_WT + (size_t)ix * NG;
                        vi += wt[j]; vf += wt[Hq + j];
                        vg += wt[2 * Hq + j]; vo += wt[3 * Hq + j];
                    }
                } else {
                    const float* pm = pin + (size_t)m * NG;
                    vi += __ldcg(&pm[j]); vf += __ldcg(&pm[Hq + j]);
                    vg += __ldcg(&pm[2 * Hq + j]); vo += __ldcg(&pm[3 * Hq + j]);
                }
                float ig = sigf(vi), fg = sigf(vf), gg = tanhf(vg), og = sigf(vo);
                float cn = fg * creg[q] + ig * gg;
                creg[q] = cn;
                float hv = og * tanhf(cn);
                __half hv16 = __float2half(hv);
                hpk[m * Hq + j] = hv16;
                if (group == 1) g_outs16[(size_t)s * Bq * Hq + m * Hq + j] = hv16;
            }
        }
        __syncthreads();

        // ---- publish completion flag ----
        if (tid == 0) {
            __threadfence();
            if (group == 0) atomicAdd(&g_fh0[s], 1);
            else if (group == 2) atomicAdd(&g_fpih[s], 1);
            else atomicAdd(&g_fh1[s], 1);
        }
    }
}

// -------- host launch --------
extern "C" void kernel_launch(void* const* d_in, const int* in_sizes, int n_in,
                              void* d_out, int out_size) {
    const float* audio  = (const float*)d_in[0];
    const int*   text   = (const int*)d_in[1];
    const float* W_proj = (const float*)d_in[2];
    const float* b_proj = (const float*)d_in[3];
    const float* W_ih0  = (const float*)d_in[4];
    const float* W_hh0  = (const float*)d_in[5];
    const float* b_ih0  = (const float*)d_in[6];
    const float* b_hh0  = (const float*)d_in[7];
    const float* W_ih1  = (const float*)d_in[8];
    const float* W_hh1  = (const float*)d_in[9];
    const float* b_ih1  = (const float*)d_in[10];
    const float* b_hh1  = (const float*)d_in[11];
    const float* W_out  = (const float*)d_in[12];
    const float* b_out  = (const float*)d_in[13];
    float* out = (float*)d_out;

    cudaFuncSetAttribute(lstm_fp16_kernel,
                         cudaFuncAttributeMaxDynamicSharedMemorySize, SMEM_BYTES);

    reset_kernel<<<1, 128>>>();
    pool_kernel<<<(Bq * DIN) / 128, 128>>>(audio);
    transpose_kernel<<<dim3(32, 128), dim3(32, 8)>>>(W_ih0);
    pack_w16_kernel<<<512, 256>>>(W_hh0, W_hh1, W_ih1, W_ih0);
    pack_wout_kernel<<<1024, 256>>>(W_out);
    gemm_enc_kernel<<<16, 256>>>(W_proj, b_proj, DIN);

    lstm_fp16_kernel<<<NPB, 256, SMEM_BYTES>>>(b_ih0, b_hh0, b_ih1, b_hh1,
                                               b_out, text, out);
}